// round 6
// baseline (speedup 1.0000x reference)
#include <cuda_runtime.h>
#include <cuda_bf16.h>
#include <math.h>

// ---------------------------------------------------------------------------
// Problem constants
// ---------------------------------------------------------------------------
#define BB   8
#define LL   4096
#define BL   (BB*LL)        // 32768
#define DD   512
#define CC   256
#define TT   2
#define HH   2
#define HDD  256
#define HC   512
#define H2   1024
#define LN_EPS 1e-5f

// ---------------------------------------------------------------------------
// Scratch (device globals; no runtime allocation allowed).
// NOTE: these symbols are NEVER passed as kernel arguments from host code
// (host-side symbol decay gives the host shadow address, which on GB300/ATS
// silently reads host memory). Kernels resolve them via gsel(id) device-side.
// ---------------------------------------------------------------------------
__device__ float g_gb[BB*1024];        // 1: gamma|beta  (film)
__device__ float g_gate[BB*DD];        // 2: sigmoid gate
__device__ float g_h[BB*HC];           // 3: gelu(ctx @ w1)
__device__ float g_ctxadd[BB*DD];      // 4: ctx @ concat_w[:,D:].T + concat_b
__device__ float g_ctxtok[BB*TT*DD];   // 5
__device__ float g_k[BB*TT*DD];        // 6
__device__ float g_v[BB*TT*DD];        // 7
__device__ float g_base[(size_t)BL*DD];// 8
__device__ float g_xq[(size_t)BL*DD];  // 9: x_q, later reused for attention out
__device__ float g_q[(size_t)BL*DD];   // 10
__device__ float g_updc[(size_t)BL*DD];// 11
__device__ float g_ao[(size_t)BL*DD];  // 12
__device__ float g_mixh[(size_t)BL*H2];// 13
__device__ float g_upda[(size_t)BL*DD];// 14
__device__ float g_w1c[1024*1536];     // 15: combined mix_w1
__device__ int   g_maskmode;           // 0 = 4-byte words, 1 = bytes (bool)

// Device-side resolver: id>0 selects a scratch global; id==0 uses the passed
// pointer (a real device pointer from d_in/d_out).
__device__ __forceinline__ float* gsel(const float* p, int id)
{
    switch (id) {
        case 1:  return g_gb;
        case 2:  return g_gate;
        case 3:  return g_h;
        case 4:  return g_ctxadd;
        case 5:  return g_ctxtok;
        case 6:  return g_k;
        case 7:  return g_v;
        case 8:  return g_base;
        case 9:  return g_xq;
        case 10: return g_q;
        case 11: return g_updc;
        case 12: return g_ao;
        case 13: return g_mixh;
        case 14: return g_upda;
        case 15: return g_w1c;
        default: return const_cast<float*>(p);
    }
}

// ---------------------------------------------------------------------------
// Mask dtype detection (robust to uint8 bool / int32 / float32 encodings).
// ---------------------------------------------------------------------------
__global__ void detect_mask_kernel(const unsigned char* __restrict__ m)
{
    __shared__ int s_gt1, s_odd;
    if (threadIdx.x == 0) { s_gt1 = 0; s_odd = 0; }
    __syncthreads();
    int lgt1 = 0, lodd = 0;
    for (int i = threadIdx.x; i < BL; i += 256) {
        unsigned char v = m[i];
        if (v > 1) lgt1 = 1;
        if ((i & 3) && v) lodd = 1;
    }
    if (lgt1) atomicOr(&s_gt1, 1);
    if (lodd) atomicOr(&s_odd, 1);
    __syncthreads();
    if (threadIdx.x == 0)
        g_maskmode = (!s_gt1 && s_odd) ? 1 : 0;
}

// ---------------------------------------------------------------------------
// Small GEMM: out[m,n] = act( sum_k A[m,k]*W[n,k] + bias[n] )
// act: 0 none, 1 gelu(exact), 2 sigmoid
// ---------------------------------------------------------------------------
__global__ void small_gemm(const float* __restrict__ Ap, int Aid, int lda,
                           const float* __restrict__ W, int ldw,
                           const float* __restrict__ bias,
                           int outid,
                           int M, int N, int K, int act)
{
    const float* A = gsel(Ap, Aid);
    float* out = gsel(nullptr, outid);
    int i = blockIdx.x * blockDim.x + threadIdx.x;
    if (i >= M * N) return;
    int m = i / N, n = i % N;
    const float* a = A + (size_t)m * lda;
    const float* w = W + (size_t)n * ldw;
    float s = 0.f;
    for (int k = 0; k < K; k++) s += a[k] * w[k];
    s += bias[n];
    if (act == 1) s = 0.5f * s * (1.f + erff(s * 0.70710678118654752f));
    else if (act == 2) s = 1.f / (1.f + expf(-s));
    out[i] = s;
}

// ---------------------------------------------------------------------------
// Build combined mix_w1:  W1c[n, 0:512]=Wa+Wc, [512:1024]=Wb-Wc, [1024:1536]=Wd
// ---------------------------------------------------------------------------
__global__ void prep_w1c(const float* __restrict__ mw1)
{
    int i = blockIdx.x * blockDim.x + threadIdx.x;
    if (i >= 1024 * 1536) return;
    int n = i / 1536, k = i % 1536;
    const float* r = mw1 + (size_t)n * 2048;
    float v;
    if      (k < 512)  v = r[k] + r[k + 1024];
    else if (k < 1024) v = r[k] - r[k + 512];
    else               v = r[k + 512];
    g_w1c[i] = v;
}

// ---------------------------------------------------------------------------
// Block reduce (128 threads) of two sums
// ---------------------------------------------------------------------------
__device__ __forceinline__ float2 block_reduce2_128(float a, float b)
{
    __shared__ float sa[4], sb[4];
    int lane = threadIdx.x & 31, w = threadIdx.x >> 5;
    #pragma unroll
    for (int o = 16; o; o >>= 1) {
        a += __shfl_down_sync(0xffffffffu, a, o);
        b += __shfl_down_sync(0xffffffffu, b, o);
    }
    if (lane == 0) { sa[w] = a; sb[w] = b; }
    __syncthreads();
    return make_float2(sa[0] + sa[1] + sa[2] + sa[3],
                       sb[0] + sb[1] + sb[2] + sb[3]);
}

// ---------------------------------------------------------------------------
// Row LN of x -> base (film) and x_q (q_ln) in one pass
// ---------------------------------------------------------------------------
__global__ void ln_base_kernel(const float* __restrict__ x,
                               const float* __restrict__ fg, const float* __restrict__ fb,
                               const float* __restrict__ qg, const float* __restrict__ qb)
{
    int row = blockIdx.x;
    int b = row >> 12;  // /4096
    const float* xr = x + (size_t)row * DD;
    float v[4], s = 0.f, s2 = 0.f;
    #pragma unroll
    for (int i = 0; i < 4; i++) {
        v[i] = xr[threadIdx.x + i * 128];
        s += v[i]; s2 += v[i] * v[i];
    }
    float2 r = block_reduce2_128(s, s2);
    float mean = r.x * (1.f / DD);
    float var  = r.y * (1.f / DD) - mean * mean;
    float inv  = rsqrtf(var + LN_EPS);
    #pragma unroll
    for (int i = 0; i < 4; i++) {
        int d = threadIdx.x + i * 128;
        float xh = (v[i] - mean) * inv;
        float lnf = xh * fg[d] + fb[d];
        float ga = g_gb[b * 1024 + d];
        float be = g_gb[b * 1024 + 512 + d];
        g_base[(size_t)row * DD + d] = (1.f + ga) * lnf + be;
        g_xq [(size_t)row * DD + d] = xh * qg[d] + qb[d];
    }
}

// ---------------------------------------------------------------------------
// In-place row LN of g_updc
// ---------------------------------------------------------------------------
__global__ void ln_updc_kernel(const float* __restrict__ g, const float* __restrict__ b)
{
    int row = blockIdx.x;
    float* sr = g_updc + (size_t)row * DD;
    float v[4], s = 0.f, s2 = 0.f;
    #pragma unroll
    for (int i = 0; i < 4; i++) {
        v[i] = sr[threadIdx.x + i * 128];
        s += v[i]; s2 += v[i] * v[i];
    }
    float2 r = block_reduce2_128(s, s2);
    float mean = r.x * (1.f / DD);
    float var  = r.y * (1.f / DD) - mean * mean;
    float inv  = rsqrtf(var + LN_EPS);
    #pragma unroll
    for (int i = 0; i < 4; i++) {
        int d = threadIdx.x + i * 128;
        sr[d] = (v[i] - mean) * inv * g[d] + b[d];
    }
}

// ---------------------------------------------------------------------------
// Attention: T=2 keys, H=2 heads, HD=256. Writes 'a' into g_xq (reuse).
// ---------------------------------------------------------------------------
__global__ void attn_kernel()
{
    int row = blockIdx.x;
    int b = row >> 12;
    int tid = threadIdx.x;
    const float* qr = g_q + (size_t)row * DD;
    const float* kb = g_k + b * (TT * DD);
    const float* vb = g_v + b * (TT * DD);

    float a00 = 0, a01 = 0, a10 = 0, a11 = 0;   // [h][t]
    {
        int d0 = tid, d1 = tid + 128, d2 = tid + 256, d3 = tid + 384;
        float q0 = qr[d0], q1 = qr[d1], q2 = qr[d2], q3 = qr[d3];
        a00 += q0 * kb[d0] + q1 * kb[d1];
        a01 += q0 * kb[512 + d0] + q1 * kb[512 + d1];
        a10 += q2 * kb[d2] + q3 * kb[d3];
        a11 += q2 * kb[512 + d2] + q3 * kb[512 + d3];
    }
    __shared__ float red[4][4];
    int lane = tid & 31, w = tid >> 5;
    #pragma unroll
    for (int o = 16; o; o >>= 1) {
        a00 += __shfl_down_sync(0xffffffffu, a00, o);
        a01 += __shfl_down_sync(0xffffffffu, a01, o);
        a10 += __shfl_down_sync(0xffffffffu, a10, o);
        a11 += __shfl_down_sync(0xffffffffu, a11, o);
    }
    if (lane == 0) { red[w][0] = a00; red[w][1] = a01; red[w][2] = a10; red[w][3] = a11; }
    __syncthreads();
    float s00 = (red[0][0] + red[1][0] + red[2][0] + red[3][0]) * 0.0625f; // /sqrt(256)
    float s01 = (red[0][1] + red[1][1] + red[2][1] + red[3][1]) * 0.0625f;
    float s10 = (red[0][2] + red[1][2] + red[2][2] + red[3][2]) * 0.0625f;
    float s11 = (red[0][3] + red[1][3] + red[2][3] + red[3][3]) * 0.0625f;

    float m0 = fmaxf(s00, s01);
    float e0a = expf(s00 - m0), e0b = expf(s01 - m0);
    float p00 = e0a / (e0a + e0b), p01 = e0b / (e0a + e0b);
    float m1 = fmaxf(s10, s11);
    float e1a = expf(s10 - m1), e1b = expf(s11 - m1);
    float p10 = e1a / (e1a + e1b), p11 = e1b / (e1a + e1b);

    float* ar = g_xq + (size_t)row * DD;
    {
        int d0 = tid, d1 = tid + 128, d2 = tid + 256, d3 = tid + 384;
        ar[d0] = p00 * vb[d0] + p01 * vb[512 + d0];
        ar[d1] = p00 * vb[d1] + p01 * vb[512 + d1];
        ar[d2] = p10 * vb[d2] + p11 * vb[512 + d2];
        ar[d3] = p10 * vb[d3] + p11 * vb[512 + d3];
    }
}

// ---------------------------------------------------------------------------
// Final: out = LN(base + gate[b]*mask*(updc+upda)) with out_ln
// ---------------------------------------------------------------------------
__global__ void final_kernel(const void* __restrict__ mask,
                             const float* __restrict__ og, const float* __restrict__ ob,
                             float* __restrict__ out)
{
    int row = blockIdx.x;
    int b = row >> 12;
    float mk;
    if (g_maskmode == 1)
        mk = ((const unsigned char*)mask)[row] ? 1.f : 0.f;
    else
        mk = (((const int*)mask)[row] != 0) ? 1.f : 0.f;
    float v[4], s = 0.f, s2 = 0.f;
    #pragma unroll
    for (int i = 0; i < 4; i++) {
        int d = threadIdx.x + i * 128;
        size_t idx = (size_t)row * DD + d;
        float val = g_base[idx] + g_gate[b * DD + d] * mk * (g_updc[idx] + g_upda[idx]);
        v[i] = val;
        s += val; s2 += val * val;
    }
    float2 r = block_reduce2_128(s, s2);
    float mean = r.x * (1.f / DD);
    float var  = r.y * (1.f / DD) - mean * mean;
    float inv  = rsqrtf(var + LN_EPS);
    #pragma unroll
    for (int i = 0; i < 4; i++) {
        int d = threadIdx.x + i * 128;
        out[(size_t)row * DD + d] = (v[i] - mean) * inv * og[d] + ob[d];
    }
}

// ---------------------------------------------------------------------------
// Main tiled GEMM:  C[m,n] = act( sum_k A[m,k]*W[n,k] + bias )
// 128x128 tile, BK=16, 256 threads, 8x8 per thread.
// All operand pointers resolved device-side via (ptr,id) pairs.
// AMODE 0: plain A.  AMODE 1: virtual A = [x | ao | x*ao] (K=1536).
// EPI   0: bias[n].  EPI   1: bias[(m>>12)*N + n] (per-batch row bias).
// ---------------------------------------------------------------------------
template<int AMODE, int EPI, bool RELU>
__global__ void __launch_bounds__(256) gemm_tn(
    const float* __restrict__ Ap, int Aid, int lda,
    int A2id,
    const float* __restrict__ Wp, int Wid, int ldb,
    const float* __restrict__ biasp, int biasid,
    int outid,
    int M, int N, int K)
{
    const float* A    = gsel(Ap, Aid);
    const float* A2   = gsel(nullptr, A2id);
    const float* W    = gsel(Wp, Wid);
    const float* bias = gsel(biasp, biasid);
    float* Cout       = gsel(nullptr, outid);

    __shared__ float As[16][128];
    __shared__ float Bs[16][128];
    const int bm = blockIdx.y * 128;
    const int bn = blockIdx.x * 128;
    const int tid = threadIdx.x;
    const int tx = tid & 15;
    const int ty = tid >> 4;

    float acc[8][8];
    #pragma unroll
    for (int i = 0; i < 8; i++)
        #pragma unroll
        for (int j = 0; j < 8; j++) acc[i][j] = 0.f;

    for (int k0 = 0; k0 < K; k0 += 16) {
        #pragma unroll
        for (int rr = 0; rr < 2; rr++) {
            int v   = tid + rr * 256;
            int row = v >> 2;
            int c4  = (v & 3) << 2;
            float4 av;
            if (AMODE == 0) {
                av = *(const float4*)&A[(size_t)(bm + row) * lda + k0 + c4];
            } else {
                int kg = k0 + c4;
                size_t rbase = (size_t)(bm + row) * 512;
                if (kg < 512) {
                    av = *(const float4*)&A[rbase + kg];
                } else if (kg < 1024) {
                    av = *(const float4*)&A2[rbase + (kg - 512)];
                } else {
                    float4 xv = *(const float4*)&A [rbase + (kg - 1024)];
                    float4 ov = *(const float4*)&A2[rbase + (kg - 1024)];
                    av = make_float4(xv.x * ov.x, xv.y * ov.y, xv.z * ov.z, xv.w * ov.w);
                }
            }
            As[c4 + 0][row] = av.x; As[c4 + 1][row] = av.y;
            As[c4 + 2][row] = av.z; As[c4 + 3][row] = av.w;
            float4 bv = *(const float4*)&W[(size_t)(bn + row) * ldb + k0 + c4];
            Bs[c4 + 0][row] = bv.x; Bs[c4 + 1][row] = bv.y;
            Bs[c4 + 2][row] = bv.z; Bs[c4 + 3][row] = bv.w;
        }
        __syncthreads();
        #pragma unroll
        for (int kk = 0; kk < 16; kk++) {
            float4 a0 = *(const float4*)&As[kk][ty * 8];
            float4 a1 = *(const float4*)&As[kk][ty * 8 + 4];
            float4 b0 = *(const float4*)&Bs[kk][tx * 8];
            float4 b1 = *(const float4*)&Bs[kk][tx * 8 + 4];
            float ar[8] = {a0.x, a0.y, a0.z, a0.w, a1.x, a1.y, a1.z, a1.w};
            float br[8] = {b0.x, b0.y, b0.z, b0.w, b1.x, b1.y, b1.z, b1.w};
            #pragma unroll
            for (int i = 0; i < 8; i++)
                #pragma unroll
                for (int j = 0; j < 8; j++)
                    acc[i][j] += ar[i] * br[j];
        }
        __syncthreads();
    }

    #pragma unroll
    for (int i = 0; i < 8; i++) {
        int m = bm + ty * 8 + i;
        int bofs = (EPI == 1) ? ((m >> 12) * N) : 0;
        #pragma unroll
        for (int j4 = 0; j4 < 2; j4++) {
            int n = bn + tx * 8 + j4 * 4;
            float4 o;
            o.x = acc[i][j4 * 4 + 0] + bias[bofs + n + 0];
            o.y = acc[i][j4 * 4 + 1] + bias[bofs + n + 1];
            o.z = acc[i][j4 * 4 + 2] + bias[bofs + n + 2];
            o.w = acc[i][j4 * 4 + 3] + bias[bofs + n + 3];
            if (RELU) {
                o.x = fmaxf(o.x, 0.f); o.y = fmaxf(o.y, 0.f);
                o.z = fmaxf(o.z, 0.f); o.w = fmaxf(o.w, 0.f);
            }
            *(float4*)&Cout[(size_t)m * N + n] = o;
        }
    }
}

// ---------------------------------------------------------------------------
// Launch
// ---------------------------------------------------------------------------
extern "C" void kernel_launch(void* const* d_in, const int* in_sizes, int n_in,
                              void* d_out, int out_size)
{
    const float* x            = (const float*)d_in[0];
    const float* context      = (const float*)d_in[1];
    const void*  pad_mask     = d_in[2];
    const float* film_ln_g    = (const float*)d_in[3];
    const float* film_ln_b    = (const float*)d_in[4];
    const float* film_w       = (const float*)d_in[5];
    const float* film_b       = (const float*)d_in[6];
    const float* concat_w     = (const float*)d_in[7];
    const float* concat_b     = (const float*)d_in[8];
    const float* concat_ln_g  = (const float*)d_in[9];
    const float* concat_ln_b  = (const float*)d_in[10];
    const float* ctx_w1       = (const float*)d_in[11];
    const float* ctx_b1       = (const float*)d_in[12];
    const float* ctx_w2       = (const float*)d_in[13];
    const float* ctx_b2       = (const float*)d_in[14];
    const float* q_ln_g       = (const float*)d_in[15];
    const float* q_ln_b       = (const float*)d_in[16];
    const float* in_proj_w    = (const float*)d_in[17];
    const float* in_proj_b    = (const float*)d_in[18];
    const float* out_proj_w   = (const float*)d_in[19];
    const float* out_proj_b   = (const float*)d_in[20];
    const float* mix_w1       = (const float*)d_in[21];
    const float* mix_b1       = (const float*)d_in[22];
    const float* mix_w2       = (const float*)d_in[23];
    const float* mix_b2       = (const float*)d_in[24];
    const float* out_ln_g     = (const float*)d_in[25];
    const float* out_ln_b     = (const float*)d_in[26];
    const float* gate_w       = (const float*)d_in[27];
    const float* gate_b       = (const float*)d_in[28];
    float* out = (float*)d_out;

    // ---- mask dtype detection ----
    detect_mask_kernel<<<1, 256>>>((const unsigned char*)pad_mask);

    // ---- tiny context-side kernels (outputs selected by id device-side) ----
    small_gemm<<<(BB*1024 + 255) / 256, 256>>>(context, 0, CC, film_w, CC, film_b, /*g_gb*/1,     BB, 1024, CC, 0);
    small_gemm<<<(BB*DD   + 255) / 256, 256>>>(context, 0, CC, gate_w, CC, gate_b, /*g_gate*/2,   BB, DD,   CC, 2);
    small_gemm<<<(BB*HC   + 255) / 256, 256>>>(context, 0, CC, ctx_w1, CC, ctx_b1, /*g_h*/3,      BB, HC,   CC, 1);
    small_gemm<<<(BB*DD   + 255) / 256, 256>>>(context, 0, CC, concat_w + DD, DD + CC, concat_b, /*g_ctxadd*/4, BB, DD, CC, 0);
    small_gemm<<<(BB*1024 + 255) / 256, 256>>>(nullptr, /*g_h*/3, HC, ctx_w2, HC, ctx_b2, /*g_ctxtok*/5, BB, 1024, HC, 0);
    small_gemm<<<(BB*TT*DD + 255) / 256, 256>>>(nullptr, /*g_ctxtok*/5, DD, in_proj_w + (size_t)DD * DD,  DD, in_proj_b + DD,   /*g_k*/6, BB*TT, DD, DD, 0);
    small_gemm<<<(BB*TT*DD + 255) / 256, 256>>>(nullptr, /*g_ctxtok*/5, DD, in_proj_w + (size_t)2*DD*DD,  DD, in_proj_b + 2*DD, /*g_v*/7, BB*TT, DD, DD, 0);
    prep_w1c<<<(1024 * 1536 + 255) / 256, 256>>>(mix_w1);

    // ---- base + x_q (one LN pass over x) ----
    ln_base_kernel<<<BL, 128>>>(x, film_ln_g, film_ln_b, q_ln_g, q_ln_b);

    // ---- q projection: g_q = g_xq @ wq.T + bq ----
    gemm_tn<0, 0, false><<<dim3(DD / 128, BL / 128), 256>>>(
        nullptr, /*A=g_xq*/9, DD, 0, in_proj_w, 0, DD, in_proj_b, 0, /*out=g_q*/10, BL, DD, DD);

    // ---- attention (writes 'a' into g_xq) ----
    attn_kernel<<<BL, 128>>>();

    // ---- out projection: g_ao = a @ out_proj_w.T + b ----
    gemm_tn<0, 0, false><<<dim3(DD / 128, BL / 128), 256>>>(
        nullptr, /*A=g_xq*/9, DD, 0, out_proj_w, 0, DD, out_proj_b, 0, /*out=g_ao*/12, BL, DD, DD);

    // ---- concat branch: relu(x @ concat_w[:, :D].T + ctxadd[b]) ----
    gemm_tn<0, 1, true><<<dim3(DD / 128, BL / 128), 256>>>(
        x, 0, DD, 0, concat_w, 0, DD + CC, nullptr, /*bias=g_ctxadd*/4, /*out=g_updc*/11, BL, DD, DD);
    ln_updc_kernel<<<BL, 128>>>(concat_ln_g, concat_ln_b);

    // ---- mix MLP: hidden = relu([x|ao|x*ao] @ W1c.T + b1) ----
    gemm_tn<1, 0, true><<<dim3(H2 / 128, BL / 128), 256>>>(
        x, 0, DD, /*A2=g_ao*/12, nullptr, /*W=g_w1c*/15, 1536, mix_b1, 0, /*out=g_mixh*/13, BL, H2, 1536);

    // ---- upd_a = hidden @ mix_w2.T + b2 ----
    gemm_tn<0, 0, false><<<dim3(DD / 128, BL / 128), 256>>>(
        nullptr, /*A=g_mixh*/13, H2, 0, mix_w2, 0, H2, mix_b2, 0, /*out=g_upda*/14, BL, DD, H2);

    // ---- final gate + LN ----
    final_kernel<<<BL, 128>>>(pad_mask, out_ln_g, out_ln_b, out);

    (void)in_sizes; (void)n_in; (void)out_size;
}

// round 8
// speedup vs baseline: 2.3814x; 2.3814x over previous
#include <cuda_runtime.h>
#include <cuda_bf16.h>
#include <math.h>
#include <stdint.h>

#define BB   8
#define LL   4096
#define BL   (BB*LL)
#define DD   512
#define CC   256
#define TT   2
#define HC   512
#define H2   1024
#define LN_EPS 1e-5f

// ---------------- fp32 scratch (ids for gsel; never passed from host) ------
__device__ float g_gb[BB*1024];          // 1
__device__ float g_gate[BB*DD];          // 2
__device__ float g_h[BB*HC];             // 3
__device__ float g_ctxadd[BB*DD];        // 4
__device__ float g_ctxtok[BB*TT*DD];     // 5
__device__ float g_k[BB*TT*DD];          // 6
__device__ float g_v[BB*TT*DD];          // 7
__device__ float g_base[(size_t)BL*DD];  // 8
__device__ float g_q[(size_t)BL*DD];     // 10
__device__ float g_updc[(size_t)BL*DD];  // 11
__device__ float g_ao[(size_t)BL*DD];    // 12
__device__ float g_upda[(size_t)BL*DD];  // 14
__device__ int   g_maskmode;

// ---------------- bf16 split scratch (ids for bsel) ------------------------
__device__ __nv_bfloat16 b_xh [(size_t)BL*DD];   // 1
__device__ __nv_bfloat16 b_xl [(size_t)BL*DD];   // 2
__device__ __nv_bfloat16 b_xqh[(size_t)BL*DD];   // 3
__device__ __nv_bfloat16 b_xql[(size_t)BL*DD];   // 4
__device__ __nv_bfloat16 b_ah [(size_t)BL*DD];   // 5
__device__ __nv_bfloat16 b_al [(size_t)BL*DD];   // 6
__device__ __nv_bfloat16 b_aoh[(size_t)BL*DD];   // 7
__device__ __nv_bfloat16 b_aol[(size_t)BL*DD];   // 8
__device__ __nv_bfloat16 b_ph [(size_t)BL*DD];   // 9
__device__ __nv_bfloat16 b_pl [(size_t)BL*DD];   // 10
__device__ __nv_bfloat16 b_mhh[(size_t)BL*H2];   // 11
__device__ __nv_bfloat16 b_mhl[(size_t)BL*H2];   // 12
__device__ __nv_bfloat16 b_wqh[DD*DD], b_wql[DD*DD];      // 13,14
__device__ __nv_bfloat16 b_woh[DD*DD], b_wol[DD*DD];      // 15,16
__device__ __nv_bfloat16 b_wch[DD*DD], b_wcl[DD*DD];      // 17,18
__device__ __nv_bfloat16 b_w1h[H2*1536], b_w1l[H2*1536];  // 19,20
__device__ __nv_bfloat16 b_w2h[DD*H2],  b_w2l[DD*H2];     // 21,22

__device__ __forceinline__ float* gsel(const float* p, int id)
{
    switch (id) {
        case 1: return g_gb;     case 2: return g_gate;   case 3: return g_h;
        case 4: return g_ctxadd; case 5: return g_ctxtok; case 6: return g_k;
        case 7: return g_v;      case 8: return g_base;   case 10: return g_q;
        case 11: return g_updc;  case 12: return g_ao;    case 14: return g_upda;
        default: return const_cast<float*>(p);
    }
}
__device__ __forceinline__ __nv_bfloat16* bsel(int id)
{
    switch (id) {
        case 1: return b_xh;   case 2: return b_xl;   case 3: return b_xqh; case 4: return b_xql;
        case 5: return b_ah;   case 6: return b_al;   case 7: return b_aoh; case 8: return b_aol;
        case 9: return b_ph;   case 10: return b_pl;  case 11: return b_mhh;case 12: return b_mhl;
        case 13: return b_wqh; case 14: return b_wql; case 15: return b_woh;case 16: return b_wol;
        case 17: return b_wch; case 18: return b_wcl; case 19: return b_w1h;case 20: return b_w1l;
        case 21: return b_w2h; case 22: return b_w2l;
        default: return nullptr;
    }
}

__device__ __forceinline__ void split2(float v, __nv_bfloat16& h, __nv_bfloat16& l)
{
    h = __float2bfloat16(v);
    l = __float2bfloat16(v - __bfloat162float(h));
}
__device__ __forceinline__ uint32_t pack2(__nv_bfloat16 a, __nv_bfloat16 b)
{
    return (uint32_t)__bfloat16_as_ushort(a) | ((uint32_t)__bfloat16_as_ushort(b) << 16);
}
__device__ __forceinline__ uint32_t smem_u32(const void* p)
{
    uint32_t a;
    asm("{ .reg .u64 t; cvta.to.shared.u64 t, %1; cvt.u32.u64 %0, t; }" : "=r"(a) : "l"(p));
    return a;
}

// ---------------- mask dtype detection -------------------------------------
__global__ void detect_mask_kernel(const unsigned char* __restrict__ m)
{
    __shared__ int s_gt1, s_odd;
    if (threadIdx.x == 0) { s_gt1 = 0; s_odd = 0; }
    __syncthreads();
    int lgt1 = 0, lodd = 0;
    for (int i = threadIdx.x; i < BL; i += 256) {
        unsigned char v = m[i];
        if (v > 1) lgt1 = 1;
        if ((i & 3) && v) lodd = 1;
    }
    if (lgt1) atomicOr(&s_gt1, 1);
    if (lodd) atomicOr(&s_odd, 1);
    __syncthreads();
    if (threadIdx.x == 0) g_maskmode = (!s_gt1 && s_odd) ? 1 : 0;
}

// ---------------- context-side small GEMM (warp per output) ----------------
__global__ void small_gemmW(const float* __restrict__ Ap, int Aid, int lda,
                            const float* __restrict__ W, int ldw,
                            const float* __restrict__ bias,
                            int outid, int M, int N, int K, int act)
{
    const float* A = gsel(Ap, Aid);
    float* out = gsel(nullptr, outid);
    int o = blockIdx.x * 8 + (threadIdx.x >> 5);
    if (o >= M * N) return;
    int lane = threadIdx.x & 31;
    int m = o / N, n = o % N;
    const float* a = A + (size_t)m * lda;
    const float* w = W + (size_t)n * ldw;
    float s = 0.f;
    for (int k = lane; k < K; k += 32) s += a[k] * w[k];
    #pragma unroll
    for (int off = 16; off; off >>= 1) s += __shfl_down_sync(0xffffffffu, s, off);
    if (lane == 0) {
        s += bias[n];
        if (act == 1)      s = 0.5f * s * (1.f + erff(s * 0.70710678118654752f));
        else if (act == 2) s = 1.f / (1.f + expf(-s));
        out[o] = s;
    }
}

// ---------------- weight / input splits ------------------------------------
__global__ void split_w_kernel(const float* __restrict__ src, int ldsrc,
                               int hiId, int loId, int total, int K)
{
    __nv_bfloat16* wh = bsel(hiId);
    __nv_bfloat16* wl = bsel(loId);
    int i = blockIdx.x * blockDim.x + threadIdx.x;
    if (i >= total) return;
    int n = i / K, k = i % K;
    float v = src[(size_t)n * ldsrc + k];
    __nv_bfloat16 h, l; split2(v, h, l);
    wh[i] = h; wl[i] = l;
}

__global__ void prep_w1c_split(const float* __restrict__ mw1)
{
    int i = blockIdx.x * blockDim.x + threadIdx.x;
    if (i >= H2 * 1536) return;
    int n = i / 1536, k = i % 1536;
    const float* r = mw1 + (size_t)n * 2048;
    float v;
    if      (k < 512)  v = r[k] + r[k + 1024];
    else if (k < 1024) v = r[k] - r[k + 512];
    else               v = r[k + 512];
    __nv_bfloat16 h, l; split2(v, h, l);
    b_w1h[i] = h; b_w1l[i] = l;
}

__global__ void split_x_kernel(const float* __restrict__ x)
{
    size_t i = (size_t)blockIdx.x * blockDim.x + threadIdx.x;
    if (i >= (size_t)BL * DD / 4) return;
    float4 v = reinterpret_cast<const float4*>(x)[i];
    __nv_bfloat16 h0,l0,h1,l1,h2,l2,h3,l3;
    split2(v.x,h0,l0); split2(v.y,h1,l1); split2(v.z,h2,l2); split2(v.w,h3,l3);
    reinterpret_cast<uint2*>(b_xh)[i] = make_uint2(pack2(h0,h1), pack2(h2,h3));
    reinterpret_cast<uint2*>(b_xl)[i] = make_uint2(pack2(l0,l1), pack2(l2,l3));
}

__global__ void prep_mix_kernel(const float* __restrict__ x)
{
    size_t i = (size_t)blockIdx.x * blockDim.x + threadIdx.x;
    if (i >= (size_t)BL * DD / 4) return;
    float4 xv = reinterpret_cast<const float4*>(x)[i];
    float4 av = reinterpret_cast<const float4*>(g_ao)[i];
    __nv_bfloat16 h0,l0,h1,l1,h2,l2,h3,l3;
    split2(av.x,h0,l0); split2(av.y,h1,l1); split2(av.z,h2,l2); split2(av.w,h3,l3);
    reinterpret_cast<uint2*>(b_aoh)[i] = make_uint2(pack2(h0,h1), pack2(h2,h3));
    reinterpret_cast<uint2*>(b_aol)[i] = make_uint2(pack2(l0,l1), pack2(l2,l3));
    split2(xv.x*av.x,h0,l0); split2(xv.y*av.y,h1,l1);
    split2(xv.z*av.z,h2,l2); split2(xv.w*av.w,h3,l3);
    reinterpret_cast<uint2*>(b_ph)[i] = make_uint2(pack2(h0,h1), pack2(h2,h3));
    reinterpret_cast<uint2*>(b_pl)[i] = make_uint2(pack2(l0,l1), pack2(l2,l3));
}

// ---------------- LN / attention / final -----------------------------------
__device__ __forceinline__ float2 block_reduce2_128(float a, float b)
{
    __shared__ float sa[4], sb[4];
    int lane = threadIdx.x & 31, w = threadIdx.x >> 5;
    #pragma unroll
    for (int o = 16; o; o >>= 1) {
        a += __shfl_down_sync(0xffffffffu, a, o);
        b += __shfl_down_sync(0xffffffffu, b, o);
    }
    if (lane == 0) { sa[w] = a; sb[w] = b; }
    __syncthreads();
    return make_float2(sa[0]+sa[1]+sa[2]+sa[3], sb[0]+sb[1]+sb[2]+sb[3]);
}

__global__ void ln_base_kernel(const float* __restrict__ x,
                               const float* __restrict__ fg, const float* __restrict__ fb,
                               const float* __restrict__ qg, const float* __restrict__ qb)
{
    int row = blockIdx.x;
    int b = row >> 12;
    const float* xr = x + (size_t)row * DD;
    float v[4], s = 0.f, s2 = 0.f;
    #pragma unroll
    for (int i = 0; i < 4; i++) {
        v[i] = xr[threadIdx.x + i * 128];
        s += v[i]; s2 += v[i] * v[i];
    }
    float2 r = block_reduce2_128(s, s2);
    float mean = r.x * (1.f / DD);
    float inv  = rsqrtf(r.y * (1.f / DD) - mean * mean + LN_EPS);
    #pragma unroll
    for (int i = 0; i < 4; i++) {
        int d = threadIdx.x + i * 128;
        float xh = (v[i] - mean) * inv;
        float lnf = xh * fg[d] + fb[d];
        g_base[(size_t)row * DD + d] = (1.f + g_gb[b*1024 + d]) * lnf + g_gb[b*1024 + 512 + d];
        float xq = xh * qg[d] + qb[d];
        __nv_bfloat16 h, l; split2(xq, h, l);
        b_xqh[(size_t)row * DD + d] = h;
        b_xql[(size_t)row * DD + d] = l;
    }
}

__global__ void ln_updc_kernel(const float* __restrict__ g, const float* __restrict__ b)
{
    int row = blockIdx.x;
    float* sr = g_updc + (size_t)row * DD;
    float v[4], s = 0.f, s2 = 0.f;
    #pragma unroll
    for (int i = 0; i < 4; i++) {
        v[i] = sr[threadIdx.x + i * 128];
        s += v[i]; s2 += v[i] * v[i];
    }
    float2 r = block_reduce2_128(s, s2);
    float mean = r.x * (1.f / DD);
    float inv  = rsqrtf(r.y * (1.f / DD) - mean * mean + LN_EPS);
    #pragma unroll
    for (int i = 0; i < 4; i++) {
        int d = threadIdx.x + i * 128;
        sr[d] = (v[i] - mean) * inv * g[d] + b[d];
    }
}

__global__ void attn_kernel()
{
    int row = blockIdx.x;
    int b = row >> 12;
    int tid = threadIdx.x;
    const float* qr = g_q + (size_t)row * DD;
    const float* kb = g_k + b * (TT * DD);
    const float* vb = g_v + b * (TT * DD);
    int d0 = tid, d1 = tid + 128, d2 = tid + 256, d3 = tid + 384;
    float a00, a01, a10, a11;
    {
        float q0 = qr[d0], q1 = qr[d1], q2 = qr[d2], q3 = qr[d3];
        a00 = q0 * kb[d0] + q1 * kb[d1];
        a01 = q0 * kb[512 + d0] + q1 * kb[512 + d1];
        a10 = q2 * kb[d2] + q3 * kb[d3];
        a11 = q2 * kb[512 + d2] + q3 * kb[512 + d3];
    }
    __shared__ float red[4][4];
    int lane = tid & 31, w = tid >> 5;
    #pragma unroll
    for (int o = 16; o; o >>= 1) {
        a00 += __shfl_down_sync(0xffffffffu, a00, o);
        a01 += __shfl_down_sync(0xffffffffu, a01, o);
        a10 += __shfl_down_sync(0xffffffffu, a10, o);
        a11 += __shfl_down_sync(0xffffffffu, a11, o);
    }
    if (lane == 0) { red[w][0]=a00; red[w][1]=a01; red[w][2]=a10; red[w][3]=a11; }
    __syncthreads();
    float s00 = (red[0][0]+red[1][0]+red[2][0]+red[3][0]) * 0.0625f;
    float s01 = (red[0][1]+red[1][1]+red[2][1]+red[3][1]) * 0.0625f;
    float s10 = (red[0][2]+red[1][2]+red[2][2]+red[3][2]) * 0.0625f;
    float s11 = (red[0][3]+red[1][3]+red[2][3]+red[3][3]) * 0.0625f;
    float m0 = fmaxf(s00, s01), m1 = fmaxf(s10, s11);
    float e0a = expf(s00-m0), e0b = expf(s01-m0);
    float e1a = expf(s10-m1), e1b = expf(s11-m1);
    float p00 = e0a/(e0a+e0b), p01 = e0b/(e0a+e0b);
    float p10 = e1a/(e1a+e1b), p11 = e1b/(e1a+e1b);
    size_t rb = (size_t)row * DD;
    __nv_bfloat16 h, l;
    float o0 = p00*vb[d0] + p01*vb[512+d0]; split2(o0,h,l); b_ah[rb+d0]=h; b_al[rb+d0]=l;
    float o1 = p00*vb[d1] + p01*vb[512+d1]; split2(o1,h,l); b_ah[rb+d1]=h; b_al[rb+d1]=l;
    float o2 = p10*vb[d2] + p11*vb[512+d2]; split2(o2,h,l); b_ah[rb+d2]=h; b_al[rb+d2]=l;
    float o3 = p10*vb[d3] + p11*vb[512+d3]; split2(o3,h,l); b_ah[rb+d3]=h; b_al[rb+d3]=l;
}

__global__ void final_kernel(const void* __restrict__ mask,
                             const float* __restrict__ og, const float* __restrict__ ob,
                             float* __restrict__ out)
{
    int row = blockIdx.x;
    int b = row >> 12;
    float mk = (g_maskmode == 1) ? (((const unsigned char*)mask)[row] ? 1.f : 0.f)
                                 : ((((const int*)mask)[row] != 0) ? 1.f : 0.f);
    float v[4], s = 0.f, s2 = 0.f;
    #pragma unroll
    for (int i = 0; i < 4; i++) {
        int d = threadIdx.x + i * 128;
        size_t idx = (size_t)row * DD + d;
        float val = g_base[idx] + g_gate[b*DD + d] * mk * (g_updc[idx] + g_upda[idx]);
        v[i] = val; s += val; s2 += val * val;
    }
    float2 r = block_reduce2_128(s, s2);
    float mean = r.x * (1.f / DD);
    float inv  = rsqrtf(r.y * (1.f / DD) - mean * mean + LN_EPS);
    #pragma unroll
    for (int i = 0; i < 4; i++) {
        int d = threadIdx.x + i * 128;
        out[(size_t)row * DD + d] = (v[i] - mean) * inv * og[d] + ob[d];
    }
}

// ---------------- mma.sync split-bf16 GEMM ----------------------------------
// C[BL, N] = (Ah+Al) @ (Wh+Wl)^T, fp32 acc: AhWh + AlWh + AhWl.
// 128x128 block tile, 8 warps (2x4), each 64x32, k-chunk 32, cp.async double buf.
// smem tile layout: rows of 32 bf16 stored as 16 uint32 with row stride 20
// (banks r*20+q mod 32 all-distinct for r=0..7 fragment reads).
#define TSTRIDE 20
#define TILE_U32 (128*TSTRIDE)
#define TILE_B   (TILE_U32*4)
#define GM_SMEM  (8*TILE_B)

__device__ __forceinline__ void cpa16(uint32_t dst, const void* src)
{
    asm volatile("cp.async.cg.shared.global [%0], [%1], 16;" :: "r"(dst), "l"(src) : "memory");
}

__device__ __forceinline__ void load_tile_async(const __nv_bfloat16* __restrict__ src, int ld,
                                                int row0, int k0, uint32_t dstb, int tid)
{
    #pragma unroll
    for (int i = 0; i < 2; i++) {
        int idx = i * 256 + tid;          // 0..511
        int rr = idx >> 2;                // 0..127
        int q  = idx & 3;                 // 16B quarter
        cpa16(dstb + rr * (TSTRIDE*4) + q * 16,
              src + (size_t)(row0 + rr) * ld + k0 + q * 8);
    }
}

__device__ __forceinline__ void mma_bf16(float* c, const uint32_t* a, const uint32_t* b)
{
    asm volatile(
        "mma.sync.aligned.m16n8k16.row.col.f32.bf16.bf16.f32 "
        "{%0,%1,%2,%3}, {%4,%5,%6,%7}, {%8,%9}, {%0,%1,%2,%3};"
        : "+f"(c[0]), "+f"(c[1]), "+f"(c[2]), "+f"(c[3])
        : "r"(a[0]), "r"(a[1]), "r"(a[2]), "r"(a[3]), "r"(b[0]), "r"(b[1]));
}

template<int AMODE, int EPI, bool RELU, int OMODE>
__global__ void __launch_bounds__(256, 1) gemm_mma(
    int AhiId, int AloId, int WhiId, int WloId,
    const float* __restrict__ biasPtr,
    int outId, int outLoId, int N, int K)
{
    extern __shared__ uint32_t sm[];
    const int tid  = threadIdx.x;
    const int wid  = tid >> 5;
    const int lane = tid & 31;
    const int wm   = wid >> 2;        // 0..1
    const int wn   = wid & 3;         // 0..3
    const int grp  = lane >> 2;       // 0..7
    const int tig  = lane & 3;        // 0..3
    const int bm   = blockIdx.y * 128;
    const int bn   = blockIdx.x * 128;

    const __nv_bfloat16* Whi = bsel(WhiId);
    const __nv_bfloat16* Wlo = bsel(WloId);
    const __nv_bfloat16* Ahi = (AMODE == 0) ? bsel(AhiId) : nullptr;
    const __nv_bfloat16* Alo = (AMODE == 0) ? bsel(AloId) : nullptr;

    const uint32_t smb = smem_u32(sm);
    const int NCH = K >> 5;

    float acc[4][4][4];
    #pragma unroll
    for (int i = 0; i < 4; i++)
        #pragma unroll
        for (int j = 0; j < 4; j++)
            #pragma unroll
            for (int q = 0; q < 4; q++) acc[i][j][q] = 0.f;

    auto issue_chunk = [&](int c) {
        const int buf = c & 1;
        const __nv_bfloat16 *pAh, *pAl; int ka, lda;
        if (AMODE == 0) { pAh = Ahi; pAl = Alo; ka = c * 32; lda = K; }
        else {
            int kg = c * 32, seg = kg >> 9; ka = kg & 511; lda = 512;
            if      (seg == 0) { pAh = b_xh;  pAl = b_xl;  }
            else if (seg == 1) { pAh = b_aoh; pAl = b_aol; }
            else               { pAh = b_ph;  pAl = b_pl;  }
        }
        uint32_t base = smb + buf * 4 * TILE_B;
        load_tile_async(pAh, lda, bm, ka,   base,            tid);
        load_tile_async(pAl, lda, bm, ka,   base +   TILE_B, tid);
        load_tile_async(Whi, K,   bn, c*32, base + 2*TILE_B, tid);
        load_tile_async(Wlo, K,   bn, c*32, base + 3*TILE_B, tid);
        asm volatile("cp.async.commit_group;" ::: "memory");
    };

    issue_chunk(0);
    asm volatile("cp.async.wait_group 0;" ::: "memory");
    __syncthreads();

    for (int c = 0; c < NCH; c++) {
        const int buf = c & 1;
        if (c + 1 < NCH) issue_chunk(c + 1);

        const uint32_t* sAh = sm + (buf * 4 + 0) * TILE_U32;
        const uint32_t* sAl = sm + (buf * 4 + 1) * TILE_U32;
        const uint32_t* sWh = sm + (buf * 4 + 2) * TILE_U32;
        const uint32_t* sWl = sm + (buf * 4 + 3) * TILE_U32;

        #pragma unroll
        for (int ks = 0; ks < 2; ks++) {
            const int kofs = ks * 8 + tig;
            uint32_t ah[4][4], al[4][4], wh[4][2], wl[4][2];
            #pragma unroll
            for (int mi = 0; mi < 4; mi++) {
                int r0 = (wm * 64 + mi * 16 + grp) * TSTRIDE + kofs;
                ah[mi][0] = sAh[r0];               ah[mi][2] = sAh[r0 + 4];
                ah[mi][1] = sAh[r0 + 8*TSTRIDE];   ah[mi][3] = sAh[r0 + 8*TSTRIDE + 4];
                al[mi][0] = sAl[r0];               al[mi][2] = sAl[r0 + 4];
                al[mi][1] = sAl[r0 + 8*TSTRIDE];   al[mi][3] = sAl[r0 + 8*TSTRIDE + 4];
            }
            #pragma unroll
            for (int nj = 0; nj < 4; nj++) {
                int n0 = (wn * 32 + nj * 8 + grp) * TSTRIDE + kofs;
                wh[nj][0] = sWh[n0]; wh[nj][1] = sWh[n0 + 4];
                wl[nj][0] = sWl[n0]; wl[nj][1] = sWl[n0 + 4];
            }
            #pragma unroll
            for (int mi = 0; mi < 4; mi++)
                #pragma unroll
                for (int nj = 0; nj < 4; nj++) {
                    mma_bf16(acc[mi][nj], ah[mi], wh[nj]);
                    mma_bf16(acc[mi][nj], al[mi], wh[nj]);
                    mma_bf16(acc[mi][nj], ah[mi], wl[nj]);
                }
        }
        asm volatile("cp.async.wait_group 0;" ::: "memory");
        __syncthreads();
    }

    // epilogue
    float* Cf = (OMODE == 0) ? gsel(nullptr, outId) : nullptr;
    __nv_bfloat16* Oh = (OMODE == 1) ? bsel(outId)   : nullptr;
    __nv_bfloat16* Ol = (OMODE == 1) ? bsel(outLoId) : nullptr;

    #pragma unroll
    for (int mi = 0; mi < 4; mi++) {
        #pragma unroll
        for (int nj = 0; nj < 4; nj++) {
            int n = bn + wn * 32 + nj * 8 + tig * 2;
            #pragma unroll
            for (int half = 0; half < 2; half++) {
                int m = bm + wm * 64 + mi * 16 + grp + half * 8;
                float v0 = acc[mi][nj][half * 2 + 0];
                float v1 = acc[mi][nj][half * 2 + 1];
                float bv0, bv1;
                if (EPI == 0) { bv0 = biasPtr[n]; bv1 = biasPtr[n + 1]; }
                else { bv0 = g_ctxadd[(m >> 12) * DD + n]; bv1 = g_ctxadd[(m >> 12) * DD + n + 1]; }
                v0 += bv0; v1 += bv1;
                if (RELU) { v0 = fmaxf(v0, 0.f); v1 = fmaxf(v1, 0.f); }
                if (OMODE == 0) {
                    *reinterpret_cast<float2*>(&Cf[(size_t)m * N + n]) = make_float2(v0, v1);
                } else {
                    __nv_bfloat16 h0, l0, h1, l1;
                    split2(v0, h0, l0); split2(v1, h1, l1);
                    *reinterpret_cast<uint32_t*>(&Oh[(size_t)m * N + n]) = pack2(h0, h1);
                    *reinterpret_cast<uint32_t*>(&Ol[(size_t)m * N + n]) = pack2(l0, l1);
                }
            }
        }
    }
}

// ---------------- launch ----------------------------------------------------
extern "C" void kernel_launch(void* const* d_in, const int* in_sizes, int n_in,
                              void* d_out, int out_size)
{
    const float* x          = (const float*)d_in[0];
    const float* context    = (const float*)d_in[1];
    const void*  pad_mask   = d_in[2];
    const float* film_ln_g  = (const float*)d_in[3];
    const float* film_ln_b  = (const float*)d_in[4];
    const float* film_w     = (const float*)d_in[5];
    const float* film_b     = (const float*)d_in[6];
    const float* concat_w   = (const float*)d_in[7];
    const float* concat_b   = (const float*)d_in[8];
    const float* concat_ln_g= (const float*)d_in[9];
    const float* concat_ln_b= (const float*)d_in[10];
    const float* ctx_w1     = (const float*)d_in[11];
    const float* ctx_b1     = (const float*)d_in[12];
    const float* ctx_w2     = (const float*)d_in[13];
    const float* ctx_b2     = (const float*)d_in[14];
    const float* q_ln_g     = (const float*)d_in[15];
    const float* q_ln_b     = (const float*)d_in[16];
    const float* in_proj_w  = (const float*)d_in[17];
    const float* in_proj_b  = (const float*)d_in[18];
    const float* out_proj_w = (const float*)d_in[19];
    const float* out_proj_b = (const float*)d_in[20];
    const float* mix_w1     = (const float*)d_in[21];
    const float* mix_b1     = (const float*)d_in[22];
    const float* mix_w2     = (const float*)d_in[23];
    const float* mix_b2     = (const float*)d_in[24];
    const float* out_ln_g   = (const float*)d_in[25];
    const float* out_ln_b   = (const float*)d_in[26];
    const float* gate_w     = (const float*)d_in[27];
    const float* gate_b     = (const float*)d_in[28];
    float* out = (float*)d_out;

    cudaFuncSetAttribute(gemm_mma<0,0,false,0>, cudaFuncAttributeMaxDynamicSharedMemorySize, GM_SMEM);
    cudaFuncSetAttribute(gemm_mma<0,1,true, 0>, cudaFuncAttributeMaxDynamicSharedMemorySize, GM_SMEM);
    cudaFuncSetAttribute(gemm_mma<1,0,true, 1>, cudaFuncAttributeMaxDynamicSharedMemorySize, GM_SMEM);

    detect_mask_kernel<<<1, 256>>>((const unsigned char*)pad_mask);

    // context-side (warp per output)
    small_gemmW<<<(BB*1024+7)/8, 256>>>(context, 0, CC, film_w, CC, film_b, 1, BB, 1024, CC, 0);
    small_gemmW<<<(BB*DD  +7)/8, 256>>>(context, 0, CC, gate_w, CC, gate_b, 2, BB, DD,   CC, 2);
    small_gemmW<<<(BB*HC  +7)/8, 256>>>(context, 0, CC, ctx_w1, CC, ctx_b1, 3, BB, HC,   CC, 1);
    small_gemmW<<<(BB*DD  +7)/8, 256>>>(context, 0, CC, concat_w + DD, DD+CC, concat_b, 4, BB, DD, CC, 0);
    small_gemmW<<<(BB*1024+7)/8, 256>>>(nullptr, 3, HC, ctx_w2, HC, ctx_b2, 5, BB, 1024, HC, 0);
    small_gemmW<<<(BB*TT*DD+7)/8, 256>>>(nullptr, 5, DD, in_proj_w + (size_t)DD*DD,   DD, in_proj_b + DD,   6, BB*TT, DD, DD, 0);
    small_gemmW<<<(BB*TT*DD+7)/8, 256>>>(nullptr, 5, DD, in_proj_w + (size_t)2*DD*DD, DD, in_proj_b + 2*DD, 7, BB*TT, DD, DD, 0);

    // weight and input splits
    split_w_kernel<<<(DD*DD+255)/256, 256>>>(in_proj_w,  DD,    13, 14, DD*DD, DD);
    split_w_kernel<<<(DD*DD+255)/256, 256>>>(out_proj_w, DD,    15, 16, DD*DD, DD);
    split_w_kernel<<<(DD*DD+255)/256, 256>>>(concat_w,   DD+CC, 17, 18, DD*DD, DD);
    split_w_kernel<<<(DD*H2+255)/256, 256>>>(mix_w2,     H2,    21, 22, DD*H2, H2);
    prep_w1c_split<<<(H2*1536+255)/256, 256>>>(mix_w1);
    split_x_kernel<<<(BL*DD/4+255)/256, 256>>>(x);

    // base + xq splits
    ln_base_kernel<<<BL, 128>>>(x, film_ln_g, film_ln_b, q_ln_g, q_ln_b);

    // q = xq @ wq^T + bq
    gemm_mma<0,0,false,0><<<dim3(4, 256), 256, GM_SMEM>>>(3, 4, 13, 14, in_proj_b, 10, 0, DD, DD);

    attn_kernel<<<BL, 128>>>();

    // ao = a @ wo^T + bo (fp32; needed for x*ao)
    gemm_mma<0,0,false,0><<<dim3(4, 256), 256, GM_SMEM>>>(5, 6, 15, 16, out_proj_b, 12, 0, DD, DD);
    prep_mix_kernel<<<(BL*DD/4+255)/256, 256>>>(x);

    // updc = relu(x @ wc^T + ctxadd[b]) then LN
    gemm_mma<0,1,true,0><<<dim3(4, 256), 256, GM_SMEM>>>(1, 2, 17, 18, nullptr, 11, 0, DD, DD);
    ln_updc_kernel<<<BL, 128>>>(concat_ln_g, concat_ln_b);

    // mixh = relu([x|ao|x*ao] @ W1c^T + b1), bf16-split output
    gemm_mma<1,0,true,1><<<dim3(8, 256), 256, GM_SMEM>>>(0, 0, 19, 20, mix_b1, 11, 12, H2, 1536);

    // upda = mixh @ w2^T + b2
    gemm_mma<0,0,false,0><<<dim3(4, 256), 256, GM_SMEM>>>(11, 12, 21, 22, mix_b2, 14, 0, DD, H2);

    final_kernel<<<BL, 128>>>(pad_mask, out_ln_g, out_ln_b, out);

    (void)in_sizes; (void)n_in; (void)out_size;
}

// round 9
// speedup vs baseline: 2.4239x; 1.0179x over previous
#include <cuda_runtime.h>
#include <cuda_bf16.h>
#include <math.h>
#include <stdint.h>

#define BB   8
#define LL   4096
#define BL   (BB*LL)
#define DD   512
#define CC   256
#define TT   2
#define HC   512
#define H2   1024
#define LN_EPS 1e-5f

// ---------------- fp32 scratch (ids for gsel; never passed from host) ------
__device__ float g_gb[BB*1024];          // 1
__device__ float g_gate[BB*DD];          // 2
__device__ float g_h[BB*HC];             // 3
__device__ float g_ctxadd[BB*DD];        // 4
__device__ float g_ctxtok[BB*TT*DD];     // 5
__device__ float g_k[BB*TT*DD];          // 6
__device__ float g_v[BB*TT*DD];          // 7
__device__ float g_base[(size_t)BL*DD];  // 8
__device__ float g_q[(size_t)BL*DD];     // 10
__device__ float g_updc[(size_t)BL*DD];  // 11
__device__ float g_ao[(size_t)BL*DD];    // 12
__device__ float g_upda[(size_t)BL*DD];  // 14
__device__ int   g_maskmode;

// ---------------- bf16 split scratch (ids for bsel) ------------------------
__device__ __nv_bfloat16 b_xh [(size_t)BL*DD];   // 1
__device__ __nv_bfloat16 b_xl [(size_t)BL*DD];   // 2
__device__ __nv_bfloat16 b_xqh[(size_t)BL*DD];   // 3
__device__ __nv_bfloat16 b_xql[(size_t)BL*DD];   // 4
__device__ __nv_bfloat16 b_ah [(size_t)BL*DD];   // 5
__device__ __nv_bfloat16 b_al [(size_t)BL*DD];   // 6
__device__ __nv_bfloat16 b_aoh[(size_t)BL*DD];   // 7
__device__ __nv_bfloat16 b_aol[(size_t)BL*DD];   // 8
__device__ __nv_bfloat16 b_ph [(size_t)BL*DD];   // 9
__device__ __nv_bfloat16 b_pl [(size_t)BL*DD];   // 10
__device__ __nv_bfloat16 b_mhh[(size_t)BL*H2];   // 11
__device__ __nv_bfloat16 b_mhl[(size_t)BL*H2];   // 12
__device__ __nv_bfloat16 b_wqh[DD*DD], b_wql[DD*DD];      // 13,14
__device__ __nv_bfloat16 b_woh[DD*DD], b_wol[DD*DD];      // 15,16
__device__ __nv_bfloat16 b_wch[DD*DD], b_wcl[DD*DD];      // 17,18
__device__ __nv_bfloat16 b_w1h[H2*1536], b_w1l[H2*1536];  // 19,20
__device__ __nv_bfloat16 b_w2h[DD*H2],  b_w2l[DD*H2];     // 21,22

__device__ __forceinline__ float* gsel(const float* p, int id)
{
    switch (id) {
        case 1: return g_gb;     case 2: return g_gate;   case 3: return g_h;
        case 4: return g_ctxadd; case 5: return g_ctxtok; case 6: return g_k;
        case 7: return g_v;      case 8: return g_base;   case 10: return g_q;
        case 11: return g_updc;  case 12: return g_ao;    case 14: return g_upda;
        default: return const_cast<float*>(p);
    }
}
__device__ __forceinline__ __nv_bfloat16* bsel(int id)
{
    switch (id) {
        case 1: return b_xh;   case 2: return b_xl;   case 3: return b_xqh; case 4: return b_xql;
        case 5: return b_ah;   case 6: return b_al;   case 7: return b_aoh; case 8: return b_aol;
        case 9: return b_ph;   case 10: return b_pl;  case 11: return b_mhh;case 12: return b_mhl;
        case 13: return b_wqh; case 14: return b_wql; case 15: return b_woh;case 16: return b_wol;
        case 17: return b_wch; case 18: return b_wcl; case 19: return b_w1h;case 20: return b_w1l;
        case 21: return b_w2h; case 22: return b_w2l;
        default: return nullptr;
    }
}

__device__ __forceinline__ void split2(float v, __nv_bfloat16& h, __nv_bfloat16& l)
{
    h = __float2bfloat16(v);
    l = __float2bfloat16(v - __bfloat162float(h));
}
__device__ __forceinline__ uint32_t pack2(__nv_bfloat16 a, __nv_bfloat16 b)
{
    return (uint32_t)__bfloat16_as_ushort(a) | ((uint32_t)__bfloat16_as_ushort(b) << 16);
}
__device__ __forceinline__ uint32_t smem_u32(const void* p)
{
    uint32_t a;
    asm("{ .reg .u64 t; cvta.to.shared.u64 t, %1; cvt.u32.u64 %0, t; }" : "=r"(a) : "l"(p));
    return a;
}

// ---------------- mask dtype detection -------------------------------------
__global__ void detect_mask_kernel(const unsigned char* __restrict__ m)
{
    __shared__ int s_gt1, s_odd;
    if (threadIdx.x == 0) { s_gt1 = 0; s_odd = 0; }
    __syncthreads();
    int lgt1 = 0, lodd = 0;
    for (int i = threadIdx.x; i < BL; i += 256) {
        unsigned char v = m[i];
        if (v > 1) lgt1 = 1;
        if ((i & 3) && v) lodd = 1;
    }
    if (lgt1) atomicOr(&s_gt1, 1);
    if (lodd) atomicOr(&s_odd, 1);
    __syncthreads();
    if (threadIdx.x == 0) g_maskmode = (!s_gt1 && s_odd) ? 1 : 0;
}

// ---------------- context-side small GEMM (warp per output) ----------------
__global__ void small_gemmW(const float* __restrict__ Ap, int Aid, int lda,
                            const float* __restrict__ W, int ldw,
                            const float* __restrict__ bias,
                            int outid, int M, int N, int K, int act)
{
    const float* A = gsel(Ap, Aid);
    float* out = gsel(nullptr, outid);
    int o = blockIdx.x * 8 + (threadIdx.x >> 5);
    if (o >= M * N) return;
    int lane = threadIdx.x & 31;
    int m = o / N, n = o % N;
    const float* a = A + (size_t)m * lda;
    const float* w = W + (size_t)n * ldw;
    float s = 0.f;
    for (int k = lane; k < K; k += 32) s += a[k] * w[k];
    #pragma unroll
    for (int off = 16; off; off >>= 1) s += __shfl_down_sync(0xffffffffu, s, off);
    if (lane == 0) {
        s += bias[n];
        if (act == 1)      s = 0.5f * s * (1.f + erff(s * 0.70710678118654752f));
        else if (act == 2) s = 1.f / (1.f + expf(-s));
        out[o] = s;
    }
}

// ---------------- weight splits --------------------------------------------
__global__ void split_w_kernel(const float* __restrict__ src, int ldsrc,
                               int hiId, int loId, int total, int K)
{
    __nv_bfloat16* wh = bsel(hiId);
    __nv_bfloat16* wl = bsel(loId);
    int i = blockIdx.x * blockDim.x + threadIdx.x;
    if (i >= total) return;
    int n = i / K, k = i % K;
    float v = src[(size_t)n * ldsrc + k];
    __nv_bfloat16 h, l; split2(v, h, l);
    wh[i] = h; wl[i] = l;
}

__global__ void prep_w1c_split(const float* __restrict__ mw1)
{
    int i = blockIdx.x * blockDim.x + threadIdx.x;
    if (i >= H2 * 1536) return;
    int n = i / 1536, k = i % 1536;
    const float* r = mw1 + (size_t)n * 2048;
    float v;
    if      (k < 512)  v = r[k] + r[k + 1024];
    else if (k < 1024) v = r[k] - r[k + 512];
    else               v = r[k + 512];
    __nv_bfloat16 h, l; split2(v, h, l);
    b_w1h[i] = h; b_w1l[i] = l;
}

__global__ void prep_mix_kernel(const float* __restrict__ x)
{
    size_t i = (size_t)blockIdx.x * blockDim.x + threadIdx.x;
    if (i >= (size_t)BL * DD / 4) return;
    float4 xv = reinterpret_cast<const float4*>(x)[i];
    float4 av = reinterpret_cast<const float4*>(g_ao)[i];
    __nv_bfloat16 h0,l0,h1,l1,h2,l2,h3,l3;
    split2(av.x,h0,l0); split2(av.y,h1,l1); split2(av.z,h2,l2); split2(av.w,h3,l3);
    reinterpret_cast<uint2*>(b_aoh)[i] = make_uint2(pack2(h0,h1), pack2(h2,h3));
    reinterpret_cast<uint2*>(b_aol)[i] = make_uint2(pack2(l0,l1), pack2(l2,l3));
    split2(xv.x*av.x,h0,l0); split2(xv.y*av.y,h1,l1);
    split2(xv.z*av.z,h2,l2); split2(xv.w*av.w,h3,l3);
    reinterpret_cast<uint2*>(b_ph)[i] = make_uint2(pack2(h0,h1), pack2(h2,h3));
    reinterpret_cast<uint2*>(b_pl)[i] = make_uint2(pack2(l0,l1), pack2(l2,l3));
}

// ---------------- LN / attention / final -----------------------------------
__device__ __forceinline__ float2 block_reduce2_128(float a, float b)
{
    __shared__ float sa[4], sb[4];
    __syncthreads();
    int lane = threadIdx.x & 31, w = threadIdx.x >> 5;
    #pragma unroll
    for (int o = 16; o; o >>= 1) {
        a += __shfl_down_sync(0xffffffffu, a, o);
        b += __shfl_down_sync(0xffffffffu, b, o);
    }
    if (lane == 0) { sa[w] = a; sb[w] = b; }
    __syncthreads();
    return make_float2(sa[0]+sa[1]+sa[2]+sa[3], sb[0]+sb[1]+sb[2]+sb[3]);
}

__global__ void ln_base_kernel(const float* __restrict__ x,
                               const float* __restrict__ fg, const float* __restrict__ fb,
                               const float* __restrict__ qg, const float* __restrict__ qb)
{
    int row = blockIdx.x;
    int b = row >> 12;
    const float* xr = x + (size_t)row * DD;
    float v[4], s = 0.f, s2 = 0.f;
    #pragma unroll
    for (int i = 0; i < 4; i++) {
        v[i] = xr[threadIdx.x + i * 128];
        s += v[i]; s2 += v[i] * v[i];
    }
    float2 r = block_reduce2_128(s, s2);
    float mean = r.x * (1.f / DD);
    float inv  = rsqrtf(r.y * (1.f / DD) - mean * mean + LN_EPS);
    #pragma unroll
    for (int i = 0; i < 4; i++) {
        int d = threadIdx.x + i * 128;
        size_t idx = (size_t)row * DD + d;
        __nv_bfloat16 h, l;
        split2(v[i], h, l);
        b_xh[idx] = h; b_xl[idx] = l;
        float xh = (v[i] - mean) * inv;
        float lnf = xh * fg[d] + fb[d];
        g_base[idx] = (1.f + g_gb[b*1024 + d]) * lnf + g_gb[b*1024 + 512 + d];
        float xq = xh * qg[d] + qb[d];
        split2(xq, h, l);
        b_xqh[idx] = h; b_xql[idx] = l;
    }
}

__global__ void attn_kernel()
{
    int row = blockIdx.x;
    int b = row >> 12;
    int tid = threadIdx.x;
    const float* qr = g_q + (size_t)row * DD;
    const float* kb = g_k + b * (TT * DD);
    const float* vb = g_v + b * (TT * DD);
    int d0 = tid, d1 = tid + 128, d2 = tid + 256, d3 = tid + 384;
    float a00, a01, a10, a11;
    {
        float q0 = qr[d0], q1 = qr[d1], q2 = qr[d2], q3 = qr[d3];
        a00 = q0 * kb[d0] + q1 * kb[d1];
        a01 = q0 * kb[512 + d0] + q1 * kb[512 + d1];
        a10 = q2 * kb[d2] + q3 * kb[d3];
        a11 = q2 * kb[512 + d2] + q3 * kb[512 + d3];
    }
    __shared__ float red[4][4];
    int lane = tid & 31, w = tid >> 5;
    #pragma unroll
    for (int o = 16; o; o >>= 1) {
        a00 += __shfl_down_sync(0xffffffffu, a00, o);
        a01 += __shfl_down_sync(0xffffffffu, a01, o);
        a10 += __shfl_down_sync(0xffffffffu, a10, o);
        a11 += __shfl_down_sync(0xffffffffu, a11, o);
    }
    if (lane == 0) { red[w][0]=a00; red[w][1]=a01; red[w][2]=a10; red[w][3]=a11; }
    __syncthreads();
    float s00 = (red[0][0]+red[1][0]+red[2][0]+red[3][0]) * 0.0625f;
    float s01 = (red[0][1]+red[1][1]+red[2][1]+red[3][1]) * 0.0625f;
    float s10 = (red[0][2]+red[1][2]+red[2][2]+red[3][2]) * 0.0625f;
    float s11 = (red[0][3]+red[1][3]+red[2][3]+red[3][3]) * 0.0625f;
    float m0 = fmaxf(s00, s01), m1 = fmaxf(s10, s11);
    float e0a = expf(s00-m0), e0b = expf(s01-m0);
    float e1a = expf(s10-m1), e1b = expf(s11-m1);
    float p00 = e0a/(e0a+e0b), p01 = e0b/(e0a+e0b);
    float p10 = e1a/(e1a+e1b), p11 = e1b/(e1a+e1b);
    size_t rb = (size_t)row * DD;
    __nv_bfloat16 h, l;
    float o0 = p00*vb[d0] + p01*vb[512+d0]; split2(o0,h,l); b_ah[rb+d0]=h; b_al[rb+d0]=l;
    float o1 = p00*vb[d1] + p01*vb[512+d1]; split2(o1,h,l); b_ah[rb+d1]=h; b_al[rb+d1]=l;
    float o2 = p10*vb[d2] + p11*vb[512+d2]; split2(o2,h,l); b_ah[rb+d2]=h; b_al[rb+d2]=l;
    float o3 = p10*vb[d3] + p11*vb[512+d3]; split2(o3,h,l); b_ah[rb+d3]=h; b_al[rb+d3]=l;
}

__global__ void final_kernel(const void* __restrict__ mask,
                             const float* __restrict__ cg, const float* __restrict__ cb,
                             const float* __restrict__ og, const float* __restrict__ ob,
                             float* __restrict__ out)
{
    int row = blockIdx.x;
    int b = row >> 12;
    float mk = (g_maskmode == 1) ? (((const unsigned char*)mask)[row] ? 1.f : 0.f)
                                 : ((((const int*)mask)[row] != 0) ? 1.f : 0.f);
    float u[4], us = 0.f, us2 = 0.f;
    #pragma unroll
    for (int i = 0; i < 4; i++) {
        int d = threadIdx.x + i * 128;
        u[i] = g_updc[(size_t)row * DD + d];
        us += u[i]; us2 += u[i] * u[i];
    }
    float2 ur = block_reduce2_128(us, us2);
    float umean = ur.x * (1.f / DD);
    float uinv  = rsqrtf(ur.y * (1.f / DD) - umean * umean + LN_EPS);
    float v[4], s = 0.f, s2 = 0.f;
    #pragma unroll
    for (int i = 0; i < 4; i++) {
        int d = threadIdx.x + i * 128;
        size_t idx = (size_t)row * DD + d;
        float uln = (u[i] - umean) * uinv * cg[d] + cb[d];
        float val = g_base[idx] + g_gate[b*DD + d] * mk * (uln + g_upda[idx]);
        v[i] = val; s += val; s2 += val * val;
    }
    float2 r = block_reduce2_128(s, s2);
    float mean = r.x * (1.f / DD);
    float inv  = rsqrtf(r.y * (1.f / DD) - mean * mean + LN_EPS);
    #pragma unroll
    for (int i = 0; i < 4; i++) {
        int d = threadIdx.x + i * 128;
        out[(size_t)row * DD + d] = (v[i] - mean) * inv * og[d] + ob[d];
    }
}

// ---------------- mma.sync split-bf16 GEMM (ldmatrix fragments) -------------
#define TSTRIDE 20
#define TILE_U32 (128*TSTRIDE)
#define TILE_B   (TILE_U32*4)
#define GM_SMEM  (8*TILE_B)

__device__ __forceinline__ void cpa16(uint32_t dst, const void* src)
{
    asm volatile("cp.async.cg.shared.global [%0], [%1], 16;" :: "r"(dst), "l"(src) : "memory");
}
__device__ __forceinline__ void load_tile_async(const __nv_bfloat16* __restrict__ src, int ld,
                                                int row0, int k0, uint32_t dstb, int tid)
{
    #pragma unroll
    for (int i = 0; i < 2; i++) {
        int idx = i * 256 + tid;
        int rr = idx >> 2;
        int q  = idx & 3;
        cpa16(dstb + rr * (TSTRIDE*4) + q * 16,
              src + (size_t)(row0 + rr) * ld + k0 + q * 8);
    }
}
__device__ __forceinline__ void mma_bf16(float* c, const uint32_t* a, const uint32_t* b)
{
    asm volatile(
        "mma.sync.aligned.m16n8k16.row.col.f32.bf16.bf16.f32 "
        "{%0,%1,%2,%3}, {%4,%5,%6,%7}, {%8,%9}, {%0,%1,%2,%3};"
        : "+f"(c[0]), "+f"(c[1]), "+f"(c[2]), "+f"(c[3])
        : "r"(a[0]), "r"(a[1]), "r"(a[2]), "r"(a[3]), "r"(b[0]), "r"(b[1]));
}
__device__ __forceinline__ void ldmx4(uint32_t* r, uint32_t addr)
{
    asm volatile("ldmatrix.sync.aligned.m8n8.x4.shared.b16 {%0,%1,%2,%3}, [%4];"
        : "=r"(r[0]), "=r"(r[1]), "=r"(r[2]), "=r"(r[3]) : "r"(addr));
}

template<int AMODE, int EPI, bool RELU, int OMODE>
__global__ void __launch_bounds__(256, 1) gemm_mma(
    int AhiId, int AloId, int WhiId, int WloId,
    const float* __restrict__ biasPtr,
    int outId, int outLoId, int N, int K)
{
    extern __shared__ uint32_t sm[];
    const int tid  = threadIdx.x;
    const int wid  = tid >> 5;
    const int lane = tid & 31;
    const int wm   = wid >> 2;
    const int wn   = wid & 3;
    const int grp  = lane >> 2;
    const int tig  = lane & 3;
    const int bm   = blockIdx.y * 128;
    const int bn   = blockIdx.x * 128;

    const __nv_bfloat16* Whi = bsel(WhiId);
    const __nv_bfloat16* Wlo = bsel(WloId);
    const __nv_bfloat16* Ahi = (AMODE == 0) ? bsel(AhiId) : nullptr;
    const __nv_bfloat16* Alo = (AMODE == 0) ? bsel(AloId) : nullptr;

    const uint32_t smb = smem_u32(sm);
    const int NCH = K >> 5;

    const int lrow = lane & 7;
    const int lsel = (lane >> 3) & 1;
    const int lhi  = lane >> 4;

    float acc[4][4][4];
    #pragma unroll
    for (int i = 0; i < 4; i++)
        #pragma unroll
        for (int j = 0; j < 4; j++)
            #pragma unroll
            for (int q = 0; q < 4; q++) acc[i][j][q] = 0.f;

    auto issue_chunk = [&](int c) {
        const int buf = c & 1;
        const __nv_bfloat16 *pAh, *pAl; int ka, lda;
        if (AMODE == 0) { pAh = Ahi; pAl = Alo; ka = c * 32; lda = K; }
        else {
            int kg = c * 32, seg = kg >> 9; ka = kg & 511; lda = 512;
            if      (seg == 0) { pAh = b_xh;  pAl = b_xl;  }
            else if (seg == 1) { pAh = b_aoh; pAl = b_aol; }
            else               { pAh = b_ph;  pAl = b_pl;  }
        }
        uint32_t base = smb + buf * 4 * TILE_B;
        load_tile_async(pAh, lda, bm, ka,   base,            tid);
        load_tile_async(pAl, lda, bm, ka,   base +   TILE_B, tid);
        load_tile_async(Whi, K,   bn, c*32, base + 2*TILE_B, tid);
        load_tile_async(Wlo, K,   bn, c*32, base + 3*TILE_B, tid);
        asm volatile("cp.async.commit_group;" ::: "memory");
    };

    issue_chunk(0);
    asm volatile("cp.async.wait_group 0;" ::: "memory");
    __syncthreads();

    for (int c = 0; c < NCH; c++) {
        const int buf = c & 1;
        if (c + 1 < NCH) issue_chunk(c + 1);

        const uint32_t tAh = smb + (buf * 4 + 0) * TILE_B;
        const uint32_t tAl = smb + (buf * 4 + 1) * TILE_B;
        const uint32_t tWh = smb + (buf * 4 + 2) * TILE_B;
        const uint32_t tWl = smb + (buf * 4 + 3) * TILE_B;

        #pragma unroll
        for (int ks = 0; ks < 2; ks++) {
            const uint32_t aoff = (uint32_t)((lrow + lsel * 8) * (TSTRIDE*4) + ks * 32 + lhi * 16);
            const uint32_t boff = (uint32_t)((lrow + lhi * 8) * (TSTRIDE*4) + ks * 32 + lsel * 16);

            uint32_t ah[4][4], al[4][4], wreg[2][4], wlreg[2][4];
            #pragma unroll
            for (int mi = 0; mi < 4; mi++) {
                uint32_t ro = (uint32_t)((wm * 64 + mi * 16) * (TSTRIDE*4));
                ldmx4(ah[mi], tAh + ro + aoff);
                ldmx4(al[mi], tAl + ro + aoff);
            }
            #pragma unroll
            for (int p = 0; p < 2; p++) {
                uint32_t no = (uint32_t)((wn * 32 + p * 16) * (TSTRIDE*4));
                ldmx4(wreg[p],  tWh + no + boff);
                ldmx4(wlreg[p], tWl + no + boff);
            }
            #pragma unroll
            for (int mi = 0; mi < 4; mi++)
                #pragma unroll
                for (int nj = 0; nj < 4; nj++) {
                    const uint32_t* bh = &wreg [nj >> 1][(nj & 1) * 2];
                    const uint32_t* bl = &wlreg[nj >> 1][(nj & 1) * 2];
                    mma_bf16(acc[mi][nj], ah[mi], bh);
                    mma_bf16(acc[mi][nj], al[mi], bh);
                    mma_bf16(acc[mi][nj], ah[mi], bl);
                }
        }
        asm volatile("cp.async.wait_group 0;" ::: "memory");
        __syncthreads();
    }

    float* Cf = (OMODE == 0) ? gsel(nullptr, outId) : nullptr;
    __nv_bfloat16* Oh = (OMODE == 1) ? bsel(outId)   : nullptr;
    __nv_bfloat16* Ol = (OMODE == 1) ? bsel(outLoId) : nullptr;

    #pragma unroll
    for (int mi = 0; mi < 4; mi++) {
        #pragma unroll
        for (int nj = 0; nj < 4; nj++) {
            int n = bn + wn * 32 + nj * 8 + tig * 2;
            #pragma unroll
            for (int half = 0; half < 2; half++) {
                int m = bm + wm * 64 + mi * 16 + grp + half * 8;
                float v0 = acc[mi][nj][half * 2 + 0];
                float v1 = acc[mi][nj][half * 2 + 1];
                float bv0, bv1;
                if (EPI == 0) { bv0 = biasPtr[n]; bv1 = biasPtr[n + 1]; }
                else { bv0 = g_ctxadd[(m >> 12) * DD + n]; bv1 = g_ctxadd[(m >> 12) * DD + n + 1]; }
                v0 += bv0; v1 += bv1;
                if (RELU) { v0 = fmaxf(v0, 0.f); v1 = fmaxf(v1, 0.f); }
                if (OMODE == 0) {
                    *reinterpret_cast<float2*>(&Cf[(size_t)m * N + n]) = make_float2(v0, v1);
                } else {
                    __nv_bfloat16 h0, l0, h1, l1;
                    split2(v0, h0, l0); split2(v1, h1, l1);
                    *reinterpret_cast<uint32_t*>(&Oh[(size_t)m * N + n]) = pack2(h0, h1);
                    *reinterpret_cast<uint32_t*>(&Ol[(size_t)m * N + n]) = pack2(l0, l1);
                }
            }
        }
    }
}

// ---------------- launch ----------------------------------------------------
extern "C" void kernel_launch(void* const* d_in, const int* in_sizes, int n_in,
                              void* d_out, int out_size)
{
    const float* x          = (const float*)d_in[0];
    const float* context    = (const float*)d_in[1];
    const void*  pad_mask   = d_in[2];
    const float* film_ln_g  = (const float*)d_in[3];
    const float* film_ln_b  = (const float*)d_in[4];
    const float* film_w     = (const float*)d_in[5];
    const float* film_b     = (const float*)d_in[6];
    const float* concat_w   = (const float*)d_in[7];
    const float* concat_b   = (const float*)d_in[8];
    const float* concat_ln_g= (const float*)d_in[9];
    const float* concat_ln_b= (const float*)d_in[10];
    const float* ctx_w1     = (const float*)d_in[11];
    const float* ctx_b1     = (const float*)d_in[12];
    const float* ctx_w2     = (const float*)d_in[13];
    const float* ctx_b2     = (const float*)d_in[14];
    const float* q_ln_g     = (const float*)d_in[15];
    const float* q_ln_b     = (const float*)d_in[16];
    const float* in_proj_w  = (const float*)d_in[17];
    const float* in_proj_b  = (const float*)d_in[18];
    const float* out_proj_w = (const float*)d_in[19];
    const float* out_proj_b = (const float*)d_in[20];
    const float* mix_w1     = (const float*)d_in[21];
    const float* mix_b1     = (const float*)d_in[22];
    const float* mix_w2     = (const float*)d_in[23];
    const float* mix_b2     = (const float*)d_in[24];
    const float* out_ln_g   = (const float*)d_in[25];
    const float* out_ln_b   = (const float*)d_in[26];
    const float* gate_w     = (const float*)d_in[27];
    const float* gate_b     = (const float*)d_in[28];
    float* out = (float*)d_out;

    cudaFuncSetAttribute(gemm_mma<0,0,false,0>, cudaFuncAttributeMaxDynamicSharedMemorySize, GM_SMEM);
    cudaFuncSetAttribute(gemm_mma<0,1,true, 0>, cudaFuncAttributeMaxDynamicSharedMemorySize, GM_SMEM);
    cudaFuncSetAttribute(gemm_mma<1,0,true, 1>, cudaFuncAttributeMaxDynamicSharedMemorySize, GM_SMEM);

    detect_mask_kernel<<<1, 256>>>((const unsigned char*)pad_mask);

    small_gemmW<<<(BB*1024+7)/8, 256>>>(context, 0, CC, film_w, CC, film_b, 1, BB, 1024, CC, 0);
    small_gemmW<<<(BB*DD  +7)/8, 256>>>(context, 0, CC, gate_w, CC, gate_b, 2, BB, DD,   CC, 2);
    small_gemmW<<<(BB*HC  +7)/8, 256>>>(context, 0, CC, ctx_w1, CC, ctx_b1, 3, BB, HC,   CC, 1);
    small_gemmW<<<(BB*DD  +7)/8, 256>>>(context, 0, CC, concat_w + DD, DD+CC, concat_b, 4, BB, DD, CC, 0);
    small_gemmW<<<(BB*1024+7)/8, 256>>>(nullptr, 3, HC, ctx_w2, HC, ctx_b2, 5, BB, 1024, HC, 0);
    small_gemmW<<<(BB*TT*DD+7)/8, 256>>>(nullptr, 5, DD, in_proj_w + (size_t)DD*DD,   DD, in_proj_b + DD,   6, BB*TT, DD, DD, 0);
    small_gemmW<<<(BB*TT*DD+7)/8, 256>>>(nullptr, 5, DD, in_proj_w + (size_t)2*DD*DD, DD, in_proj_b + 2*DD, 7, BB*TT, DD, DD, 0);

    split_w_kernel<<<(DD*DD+255)/256, 256>>>(in_proj_w,  DD,    13, 14, DD*DD, DD);
    split_w_kernel<<<(DD*DD+255)/256, 256>>>(out_proj_w, DD,    15, 16, DD*DD, DD);
    split_w_kernel<<<(DD*DD+255)/256, 256>>>(concat_w,   DD+CC, 17, 18, DD*DD, DD);
    split_w_kernel<<<(DD*H2+255)/256, 256>>>(mix_w2,     H2,    21, 22, DD*H2, H2);
    prep_w1c_split<<<(H2*1536+255)/256, 256>>>(mix_w1);

    ln_base_kernel<<<BL, 128>>>(x, film_ln_g, film_ln_b, q_ln_g, q_ln_b);

    gemm_mma<0,0,false,0><<<dim3(4, 256), 256, GM_SMEM>>>(3, 4, 13, 14, in_proj_b, 10, 0, DD, DD);

    attn_kernel<<<BL, 128>>>();

    gemm_mma<0,0,false,0><<<dim3(4, 256), 256, GM_SMEM>>>(5, 6, 15, 16, out_proj_b, 12, 0, DD, DD);
    prep_mix_kernel<<<(BL*DD/4+255)/256, 256>>>(x);

    gemm_mma<0,1,true,0><<<dim3(4, 256), 256, GM_SMEM>>>(1, 2, 17, 18, nullptr, 11, 0, DD, DD);

    gemm_mma<1,0,true,1><<<dim3(8, 256), 256, GM_SMEM>>>(0, 0, 19, 20, mix_b1, 11, 12, H2, 1536);

    gemm_mma<0,0,false,0><<<dim3(4, 256), 256, GM_SMEM>>>(11, 12, 21, 22, mix_b2, 14, 0, DD, H2);

    final_kernel<<<BL, 128>>>(pad_mask, concat_ln_g, concat_ln_b, out_ln_g, out_ln_b, out);

    (void)in_sizes; (void)n_in; (void)out_size;
}

// round 11
// speedup vs baseline: 4.0254x; 1.6607x over previous
#include <cuda_runtime.h>
#include <cuda_bf16.h>
#include <cuda_fp16.h>
#include <math.h>
#include <stdint.h>

#define BB   8
#define LL   4096
#define BL   (BB*LL)
#define DD   512
#define CC   256
#define TT   2
#define HC   512
#define H2   1024
#define LN_EPS 1e-5f

// ---------------- fp32 scratch (ids for gsel; never passed from host) ------
__device__ float g_gb[BB*1024];          // 1
__device__ float g_gate[BB*DD];          // 2
__device__ float g_h[BB*HC];             // 3
__device__ float g_ctxadd[BB*DD];        // 4
__device__ float g_ctxtok[BB*TT*DD];     // 5
__device__ float g_k[BB*TT*DD];          // 6
__device__ float g_v[BB*TT*DD];          // 7
__device__ float g_base[(size_t)BL*DD];  // 8
__device__ float g_q[(size_t)BL*DD];     // 10
__device__ float g_updc[(size_t)BL*DD];  // 11
__device__ float g_ao[(size_t)BL*DD];    // 12
__device__ float g_upda[(size_t)BL*DD];  // 14
__device__ int   g_maskmode;

// ---------------- fp16 split scratch (ids for hsel) -------------------------
__device__ __half h_xh [(size_t)BL*DD];   // 1
__device__ __half h_xl [(size_t)BL*DD];   // 2
__device__ __half h_xqh[(size_t)BL*DD];   // 3
__device__ __half h_xql[(size_t)BL*DD];   // 4
__device__ __half h_ah [(size_t)BL*DD];   // 5
__device__ __half h_al [(size_t)BL*DD];   // 6
__device__ __half h_aoh[(size_t)BL*DD];   // 7
__device__ __half h_aol[(size_t)BL*DD];   // 8
__device__ __half h_ph [(size_t)BL*DD];   // 9
__device__ __half h_pl [(size_t)BL*DD];   // 10
__device__ __half h_mhh[(size_t)BL*H2];   // 11
__device__ __half h_mhl[(size_t)BL*H2];   // 12
__device__ __half h_wq[DD*DD];            // 13
__device__ __half h_wo[DD*DD];            // 14
__device__ __half h_wc[DD*DD];            // 15
__device__ __half h_w1[H2*1536];          // 16
__device__ __half h_w2[DD*H2];            // 17

__device__ __forceinline__ float* gsel(const float* p, int id)
{
    switch (id) {
        case 1: return g_gb;     case 2: return g_gate;   case 3: return g_h;
        case 4: return g_ctxadd; case 5: return g_ctxtok; case 6: return g_k;
        case 7: return g_v;      case 8: return g_base;   case 10: return g_q;
        case 11: return g_updc;  case 12: return g_ao;    case 14: return g_upda;
        default: return const_cast<float*>(p);
    }
}
__device__ __forceinline__ __half* hsel(int id)
{
    switch (id) {
        case 1: return h_xh;   case 2: return h_xl;   case 3: return h_xqh; case 4: return h_xql;
        case 5: return h_ah;   case 6: return h_al;   case 7: return h_aoh; case 8: return h_aol;
        case 9: return h_ph;   case 10: return h_pl;  case 11: return h_mhh;case 12: return h_mhl;
        case 13: return h_wq;  case 14: return h_wo;  case 15: return h_wc; case 16: return h_w1;
        case 17: return h_w2;
        default: return nullptr;
    }
}

__device__ __forceinline__ void split2h(float v, __half& h, __half& l)
{
    h = __float2half_rn(v);
    l = __float2half_rn(v - __half2float(h));
}
__device__ __forceinline__ uint32_t pack2h(__half a, __half b)
{
    return (uint32_t)__half_as_ushort(a) | ((uint32_t)__half_as_ushort(b) << 16);
}
__device__ __forceinline__ uint32_t smem_u32(const void* p)
{
    uint32_t a;
    asm("{ .reg .u64 t; cvta.to.shared.u64 t, %1; cvt.u32.u64 %0, t; }" : "=r"(a) : "l"(p));
    return a;
}

// ---------------- mask dtype detection -------------------------------------
__global__ void detect_mask_kernel(const unsigned char* __restrict__ m)
{
    __shared__ int s_gt1, s_odd;
    if (threadIdx.x == 0) { s_gt1 = 0; s_odd = 0; }
    __syncthreads();
    int lgt1 = 0, lodd = 0;
    for (int i = threadIdx.x; i < BL; i += 256) {
        unsigned char v = m[i];
        if (v > 1) lgt1 = 1;
        if ((i & 3) && v) lodd = 1;
    }
    if (lgt1) atomicOr(&s_gt1, 1);
    if (lodd) atomicOr(&s_odd, 1);
    __syncthreads();
    if (threadIdx.x == 0) g_maskmode = (!s_gt1 && s_odd) ? 1 : 0;
}

// ---------------- context-side small GEMM (warp per output) ----------------
__global__ void small_gemmW(const float* __restrict__ Ap, int Aid, int lda,
                            const float* __restrict__ W, int ldw,
                            const float* __restrict__ bias,
                            int outid, int M, int N, int K, int act)
{
    const float* A = gsel(Ap, Aid);
    float* out = gsel(nullptr, outid);
    int o = blockIdx.x * 8 + (threadIdx.x >> 5);
    if (o >= M * N) return;
    int lane = threadIdx.x & 31;
    int m = o / N, n = o % N;
    const float* a = A + (size_t)m * lda;
    const float* w = W + (size_t)n * ldw;
    float s = 0.f;
    for (int k = lane; k < K; k += 32) s += a[k] * w[k];
    #pragma unroll
    for (int off = 16; off; off >>= 1) s += __shfl_down_sync(0xffffffffu, s, off);
    if (lane == 0) {
        s += bias[n];
        if (act == 1)      s = 0.5f * s * (1.f + erff(s * 0.70710678118654752f));
        else if (act == 2) s = 1.f / (1.f + expf(-s));
        out[o] = s;
    }
}

// ---------------- weight rounding (single fp16) ------------------------------
__global__ void round_w_kernel(const float* __restrict__ src, int ldsrc,
                               int wId, int total, int K)
{
    __half* wh = hsel(wId);
    int i = blockIdx.x * blockDim.x + threadIdx.x;
    if (i >= total) return;
    int n = i / K, k = i % K;
    wh[i] = __float2half_rn(src[(size_t)n * ldsrc + k]);
}

__global__ void prep_w1c_kernel(const float* __restrict__ mw1)
{
    int i = blockIdx.x * blockDim.x + threadIdx.x;
    if (i >= H2 * 1536) return;
    int n = i / 1536, k = i % 1536;
    const float* r = mw1 + (size_t)n * 2048;
    float v;
    if      (k < 512)  v = r[k] + r[k + 1024];
    else if (k < 1024) v = r[k] - r[k + 512];
    else               v = r[k + 512];
    h_w1[i] = __float2half_rn(v);
}

__global__ void prep_mix_kernel(const float* __restrict__ x)
{
    size_t i = (size_t)blockIdx.x * blockDim.x + threadIdx.x;
    if (i >= (size_t)BL * DD / 4) return;
    float4 xv = reinterpret_cast<const float4*>(x)[i];
    float4 av = reinterpret_cast<const float4*>(g_ao)[i];
    __half h0,l0,h1,l1,h2,l2,h3,l3;
    split2h(av.x,h0,l0); split2h(av.y,h1,l1); split2h(av.z,h2,l2); split2h(av.w,h3,l3);
    reinterpret_cast<uint2*>(h_aoh)[i] = make_uint2(pack2h(h0,h1), pack2h(h2,h3));
    reinterpret_cast<uint2*>(h_aol)[i] = make_uint2(pack2h(l0,l1), pack2h(l2,l3));
    split2h(xv.x*av.x,h0,l0); split2h(xv.y*av.y,h1,l1);
    split2h(xv.z*av.z,h2,l2); split2h(xv.w*av.w,h3,l3);
    reinterpret_cast<uint2*>(h_ph)[i] = make_uint2(pack2h(h0,h1), pack2h(h2,h3));
    reinterpret_cast<uint2*>(h_pl)[i] = make_uint2(pack2h(l0,l1), pack2h(l2,l3));
}

// ---------------- LN / attention / final -----------------------------------
__device__ __forceinline__ float2 block_reduce2_128(float a, float b)
{
    __shared__ float sa[4], sb[4];
    __syncthreads();
    int lane = threadIdx.x & 31, w = threadIdx.x >> 5;
    #pragma unroll
    for (int o = 16; o; o >>= 1) {
        a += __shfl_down_sync(0xffffffffu, a, o);
        b += __shfl_down_sync(0xffffffffu, b, o);
    }
    if (lane == 0) { sa[w] = a; sb[w] = b; }
    __syncthreads();
    return make_float2(sa[0]+sa[1]+sa[2]+sa[3], sb[0]+sb[1]+sb[2]+sb[3]);
}

__global__ void ln_base_kernel(const float* __restrict__ x,
                               const float* __restrict__ fg, const float* __restrict__ fb,
                               const float* __restrict__ qg, const float* __restrict__ qb)
{
    int row = blockIdx.x;
    int b = row >> 12;
    const float* xr = x + (size_t)row * DD;
    float v[4], s = 0.f, s2 = 0.f;
    #pragma unroll
    for (int i = 0; i < 4; i++) {
        v[i] = xr[threadIdx.x + i * 128];
        s += v[i]; s2 += v[i] * v[i];
    }
    float2 r = block_reduce2_128(s, s2);
    float mean = r.x * (1.f / DD);
    float inv  = rsqrtf(r.y * (1.f / DD) - mean * mean + LN_EPS);
    #pragma unroll
    for (int i = 0; i < 4; i++) {
        int d = threadIdx.x + i * 128;
        size_t idx = (size_t)row * DD + d;
        __half h, l;
        split2h(v[i], h, l);
        h_xh[idx] = h; h_xl[idx] = l;
        float xh = (v[i] - mean) * inv;
        float lnf = xh * fg[d] + fb[d];
        g_base[idx] = (1.f + g_gb[b*1024 + d]) * lnf + g_gb[b*1024 + 512 + d];
        float xq = xh * qg[d] + qb[d];
        split2h(xq, h, l);
        h_xqh[idx] = h; h_xql[idx] = l;
    }
}

__global__ void attn_kernel()
{
    int row = blockIdx.x;
    int b = row >> 12;
    int tid = threadIdx.x;
    const float* qr = g_q + (size_t)row * DD;
    const float* kb = g_k + b * (TT * DD);
    const float* vb = g_v + b * (TT * DD);
    int d0 = tid, d1 = tid + 128, d2 = tid + 256, d3 = tid + 384;
    float a00, a01, a10, a11;
    {
        float q0 = qr[d0], q1 = qr[d1], q2 = qr[d2], q3 = qr[d3];
        a00 = q0 * kb[d0] + q1 * kb[d1];
        a01 = q0 * kb[512 + d0] + q1 * kb[512 + d1];
        a10 = q2 * kb[d2] + q3 * kb[d3];
        a11 = q2 * kb[512 + d2] + q3 * kb[512 + d3];
    }
    __shared__ float red[4][4];
    int lane = tid & 31, w = tid >> 5;
    #pragma unroll
    for (int o = 16; o; o >>= 1) {
        a00 += __shfl_down_sync(0xffffffffu, a00, o);
        a01 += __shfl_down_sync(0xffffffffu, a01, o);
        a10 += __shfl_down_sync(0xffffffffu, a10, o);
        a11 += __shfl_down_sync(0xffffffffu, a11, o);
    }
    if (lane == 0) { red[w][0]=a00; red[w][1]=a01; red[w][2]=a10; red[w][3]=a11; }
    __syncthreads();
    float s00 = (red[0][0]+red[1][0]+red[2][0]+red[3][0]) * 0.0625f;
    float s01 = (red[0][1]+red[1][1]+red[2][1]+red[3][1]) * 0.0625f;
    float s10 = (red[0][2]+red[1][2]+red[2][2]+red[3][2]) * 0.0625f;
    float s11 = (red[0][3]+red[1][3]+red[2][3]+red[3][3]) * 0.0625f;
    float m0 = fmaxf(s00, s01), m1 = fmaxf(s10, s11);
    float e0a = expf(s00-m0), e0b = expf(s01-m0);
    float e1a = expf(s10-m1), e1b = expf(s11-m1);
    float p00 = e0a/(e0a+e0b), p01 = e0b/(e0a+e0b);
    float p10 = e1a/(e1a+e1b), p11 = e1b/(e1a+e1b);
    size_t rb = (size_t)row * DD;
    __half h, l;
    float o0 = p00*vb[d0] + p01*vb[512+d0]; split2h(o0,h,l); h_ah[rb+d0]=h; h_al[rb+d0]=l;
    float o1 = p00*vb[d1] + p01*vb[512+d1]; split2h(o1,h,l); h_ah[rb+d1]=h; h_al[rb+d1]=l;
    float o2 = p10*vb[d2] + p11*vb[512+d2]; split2h(o2,h,l); h_ah[rb+d2]=h; h_al[rb+d2]=l;
    float o3 = p10*vb[d3] + p11*vb[512+d3]; split2h(o3,h,l); h_ah[rb+d3]=h; h_al[rb+d3]=l;
}

__global__ void final_kernel(const void* __restrict__ mask,
                             const float* __restrict__ cg, const float* __restrict__ cb,
                             const float* __restrict__ og, const float* __restrict__ ob,
                             float* __restrict__ out)
{
    int row = blockIdx.x;
    int b = row >> 12;
    float mk = (g_maskmode == 1) ? (((const unsigned char*)mask)[row] ? 1.f : 0.f)
                                 : ((((const int*)mask)[row] != 0) ? 1.f : 0.f);
    float u[4], us = 0.f, us2 = 0.f;
    #pragma unroll
    for (int i = 0; i < 4; i++) {
        int d = threadIdx.x + i * 128;
        u[i] = g_updc[(size_t)row * DD + d];
        us += u[i]; us2 += u[i] * u[i];
    }
    float2 ur = block_reduce2_128(us, us2);
    float umean = ur.x * (1.f / DD);
    float uinv  = rsqrtf(ur.y * (1.f / DD) - umean * umean + LN_EPS);
    float v[4], s = 0.f, s2 = 0.f;
    #pragma unroll
    for (int i = 0; i < 4; i++) {
        int d = threadIdx.x + i * 128;
        size_t idx = (size_t)row * DD + d;
        float uln = (u[i] - umean) * uinv * cg[d] + cb[d];
        float val = g_base[idx] + g_gate[b*DD + d] * mk * (uln + g_upda[idx]);
        v[i] = val; s += val; s2 += val * val;
    }
    float2 r = block_reduce2_128(s, s2);
    float mean = r.x * (1.f / DD);
    float inv  = rsqrtf(r.y * (1.f / DD) - mean * mean + LN_EPS);
    #pragma unroll
    for (int i = 0; i < 4; i++) {
        int d = threadIdx.x + i * 128;
        out[(size_t)row * DD + d] = (v[i] - mean) * inv * og[d] + ob[d];
    }
}

// ---------------- mma.sync 2-pass fp16 GEMM (ldmatrix fragments) -------------
// C[BL, N] = (Ah+Al) @ Wh^T, fp32 acc. A exact (2x fp16), W rounded fp16.
// 128x128 block tile, 8 warps (2x4), each 64x32, k-chunk 32, cp.async double buf.
#define TSTRIDE 20
#define TILE_U32 (128*TSTRIDE)
#define TILE_B   (TILE_U32*4)
#define GM_SMEM  (6*TILE_B)

__device__ __forceinline__ void cpa16(uint32_t dst, const void* src)
{
    asm volatile("cp.async.cg.shared.global [%0], [%1], 16;" :: "r"(dst), "l"(src) : "memory");
}
__device__ __forceinline__ void load_tile_async(const __half* __restrict__ src, int ld,
                                                int row0, int k0, uint32_t dstb, int tid)
{
    #pragma unroll
    for (int i = 0; i < 2; i++) {
        int idx = i * 256 + tid;
        int rr = idx >> 2;
        int q  = idx & 3;
        cpa16(dstb + rr * (TSTRIDE*4) + q * 16,
              src + (size_t)(row0 + rr) * ld + k0 + q * 8);
    }
}
__device__ __forceinline__ void mma_fp16(float* c, const uint32_t* a, const uint32_t* b)
{
    asm volatile(
        "mma.sync.aligned.m16n8k16.row.col.f32.f16.f16.f32 "
        "{%0,%1,%2,%3}, {%4,%5,%6,%7}, {%8,%9}, {%0,%1,%2,%3};"
        : "+f"(c[0]), "+f"(c[1]), "+f"(c[2]), "+f"(c[3])
        : "r"(a[0]), "r"(a[1]), "r"(a[2]), "r"(a[3]), "r"(b[0]), "r"(b[1]));
}
__device__ __forceinline__ void ldmx4(uint32_t* r, uint32_t addr)
{
    asm volatile("ldmatrix.sync.aligned.m8n8.x4.shared.b16 {%0,%1,%2,%3}, [%4];"
        : "=r"(r[0]), "=r"(r[1]), "=r"(r[2]), "=r"(r[3]) : "r"(addr));
}

template<int AMODE, int EPI, bool RELU, int OMODE>
__global__ void __launch_bounds__(256, 2) gemm_mma(
    int AhiId, int AloId, int WId,
    const float* __restrict__ biasPtr,
    int outId, int outLoId, int N, int K)
{
    extern __shared__ uint32_t sm[];
    const int tid  = threadIdx.x;
    const int wid  = tid >> 5;
    const int lane = tid & 31;
    const int wm   = wid >> 2;
    const int wn   = wid & 3;
    const int grp  = lane >> 2;
    const int tig  = lane & 3;
    const int bm   = blockIdx.y * 128;
    const int bn   = blockIdx.x * 128;

    const __half* Wh  = hsel(WId);
    const __half* Ahi = (AMODE == 0) ? hsel(AhiId) : nullptr;
    const __half* Alo = (AMODE == 0) ? hsel(AloId) : nullptr;

    const uint32_t smb = smem_u32(sm);
    const int NCH = K >> 5;

    const int lrow = lane & 7;
    const int lsel = (lane >> 3) & 1;
    const int lhi  = lane >> 4;

    float acc[4][4][4];
    #pragma unroll
    for (int i = 0; i < 4; i++)
        #pragma unroll
        for (int j = 0; j < 4; j++)
            #pragma unroll
            for (int q = 0; q < 4; q++) acc[i][j][q] = 0.f;

    auto issue_chunk = [&](int c) {
        const int buf = c & 1;
        const __half *pAh, *pAl; int ka, lda;
        if (AMODE == 0) { pAh = Ahi; pAl = Alo; ka = c * 32; lda = K; }
        else {
            int kg = c * 32, seg = kg >> 9; ka = kg & 511; lda = 512;
            if      (seg == 0) { pAh = h_xh;  pAl = h_xl;  }
            else if (seg == 1) { pAh = h_aoh; pAl = h_aol; }
            else               { pAh = h_ph;  pAl = h_pl;  }
        }
        uint32_t base = smb + buf * 3 * TILE_B;
        load_tile_async(pAh, lda, bm, ka,   base,            tid);
        load_tile_async(pAl, lda, bm, ka,   base +   TILE_B, tid);
        load_tile_async(Wh,  K,   bn, c*32, base + 2*TILE_B, tid);
        asm volatile("cp.async.commit_group;" ::: "memory");
    };

    issue_chunk(0);
    asm volatile("cp.async.wait_group 0;" ::: "memory");
    __syncthreads();

    for (int c = 0; c < NCH; c++) {
        const int buf = c & 1;
        if (c + 1 < NCH) issue_chunk(c + 1);

        const uint32_t tAh = smb + (buf * 3 + 0) * TILE_B;
        const uint32_t tAl = smb + (buf * 3 + 1) * TILE_B;
        const uint32_t tWh = smb + (buf * 3 + 2) * TILE_B;

        #pragma unroll
        for (int ks = 0; ks < 2; ks++) {
            const uint32_t aoff = (uint32_t)((lrow + lsel * 8) * (TSTRIDE*4) + ks * 32 + lhi * 16);
            const uint32_t boff = (uint32_t)((lrow + lhi * 8) * (TSTRIDE*4) + ks * 32 + lsel * 16);

            uint32_t ah[4][4], al[4][4], wreg[2][4];
            #pragma unroll
            for (int mi = 0; mi < 4; mi++) {
                uint32_t ro = (uint32_t)((wm * 64 + mi * 16) * (TSTRIDE*4));
                ldmx4(ah[mi], tAh + ro + aoff);
                ldmx4(al[mi], tAl + ro + aoff);
            }
            #pragma unroll
            for (int p = 0; p < 2; p++) {
                uint32_t no = (uint32_t)((wn * 32 + p * 16) * (TSTRIDE*4));
                ldmx4(wreg[p], tWh + no + boff);
            }
            #pragma unroll
            for (int mi = 0; mi < 4; mi++)
                #pragma unroll
                for (int nj = 0; nj < 4; nj++) {
                    const uint32_t* bh = &wreg[nj >> 1][(nj & 1) * 2];
                    mma_fp16(acc[mi][nj], ah[mi], bh);
                    mma_fp16(acc[mi][nj], al[mi], bh);
                }
        }
        asm volatile("cp.async.wait_group 0;" ::: "memory");
        __syncthreads();
    }

    float* Cf = (OMODE == 0) ? gsel(nullptr, outId) : nullptr;
    __half* Oh = (OMODE == 1) ? hsel(outId)   : nullptr;
    __half* Ol = (OMODE == 1) ? hsel(outLoId) : nullptr;

    #pragma unroll
    for (int mi = 0; mi < 4; mi++) {
        #pragma unroll
        for (int nj = 0; nj < 4; nj++) {
            int n = bn + wn * 32 + nj * 8 + tig * 2;
            #pragma unroll
            for (int half = 0; half < 2; half++) {
                int m = bm + wm * 64 + mi * 16 + grp + half * 8;
                float v0 = acc[mi][nj][half * 2 + 0];
                float v1 = acc[mi][nj][half * 2 + 1];
                float bv0, bv1;
                if (EPI == 0) { bv0 = biasPtr[n]; bv1 = biasPtr[n + 1]; }
                else { bv0 = g_ctxadd[(m >> 12) * DD + n]; bv1 = g_ctxadd[(m >> 12) * DD + n + 1]; }
                v0 += bv0; v1 += bv1;
                if (RELU) { v0 = fmaxf(v0, 0.f); v1 = fmaxf(v1, 0.f); }
                if (OMODE == 0) {
                    *reinterpret_cast<float2*>(&Cf[(size_t)m * N + n]) = make_float2(v0, v1);
                } else {
                    __half h0, l0, h1, l1;
                    split2h(v0, h0, l0); split2h(v1, h1, l1);
                    *reinterpret_cast<uint32_t*>(&Oh[(size_t)m * N + n]) = pack2h(h0, h1);
                    *reinterpret_cast<uint32_t*>(&Ol[(size_t)m * N + n]) = pack2h(l0, l1);
                }
            }
        }
    }
}

// ---------------- launch ----------------------------------------------------
extern "C" void kernel_launch(void* const* d_in, const int* in_sizes, int n_in,
                              void* d_out, int out_size)
{
    const float* x          = (const float*)d_in[0];
    const float* context    = (const float*)d_in[1];
    const void*  pad_mask   = d_in[2];
    const float* film_ln_g  = (const float*)d_in[3];
    const float* film_ln_b  = (const float*)d_in[4];
    const float* film_w     = (const float*)d_in[5];
    const float* film_b     = (const float*)d_in[6];
    const float* concat_w   = (const float*)d_in[7];
    const float* concat_b   = (const float*)d_in[8];
    const float* concat_ln_g= (const float*)d_in[9];
    const float* concat_ln_b= (const float*)d_in[10];
    const float* ctx_w1     = (const float*)d_in[11];
    const float* ctx_b1     = (const float*)d_in[12];
    const float* ctx_w2     = (const float*)d_in[13];
    const float* ctx_b2     = (const float*)d_in[14];
    const float* q_ln_g     = (const float*)d_in[15];
    const float* q_ln_b     = (const float*)d_in[16];
    const float* in_proj_w  = (const float*)d_in[17];
    const float* in_proj_b  = (const float*)d_in[18];
    const float* out_proj_w = (const float*)d_in[19];
    const float* out_proj_b = (const float*)d_in[20];
    const float* mix_w1     = (const float*)d_in[21];
    const float* mix_b1     = (const float*)d_in[22];
    const float* mix_w2     = (const float*)d_in[23];
    const float* mix_b2     = (const float*)d_in[24];
    const float* out_ln_g   = (const float*)d_in[25];
    const float* out_ln_b   = (const float*)d_in[26];
    const float* gate_w     = (const float*)d_in[27];
    const float* gate_b     = (const float*)d_in[28];
    float* out = (float*)d_out;

    cudaFuncSetAttribute(gemm_mma<0,0,false,0>, cudaFuncAttributeMaxDynamicSharedMemorySize, GM_SMEM);
    cudaFuncSetAttribute(gemm_mma<0,1,true, 0>, cudaFuncAttributeMaxDynamicSharedMemorySize, GM_SMEM);
    cudaFuncSetAttribute(gemm_mma<1,0,true, 1>, cudaFuncAttributeMaxDynamicSharedMemorySize, GM_SMEM);

    detect_mask_kernel<<<1, 256>>>((const unsigned char*)pad_mask);

    small_gemmW<<<(BB*1024+7)/8, 256>>>(context, 0, CC, film_w, CC, film_b, 1, BB, 1024, CC, 0);
    small_gemmW<<<(BB*DD  +7)/8, 256>>>(context, 0, CC, gate_w, CC, gate_b, 2, BB, DD,   CC, 2);
    small_gemmW<<<(BB*HC  +7)/8, 256>>>(context, 0, CC, ctx_w1, CC, ctx_b1, 3, BB, HC,   CC, 1);
    small_gemmW<<<(BB*DD  +7)/8, 256>>>(context, 0, CC, concat_w + DD, DD+CC, concat_b, 4, BB, DD, CC, 0);
    small_gemmW<<<(BB*1024+7)/8, 256>>>(nullptr, 3, HC, ctx_w2, HC, ctx_b2, 5, BB, 1024, HC, 0);
    small_gemmW<<<(BB*TT*DD+7)/8, 256>>>(nullptr, 5, DD, in_proj_w + (size_t)DD*DD,   DD, in_proj_b + DD,   6, BB*TT, DD, DD, 0);
    small_gemmW<<<(BB*TT*DD+7)/8, 256>>>(nullptr, 5, DD, in_proj_w + (size_t)2*DD*DD, DD, in_proj_b + 2*DD, 7, BB*TT, DD, DD, 0);

    round_w_kernel<<<(DD*DD+255)/256, 256>>>(in_proj_w,  DD,    13, DD*DD, DD);
    round_w_kernel<<<(DD*DD+255)/256, 256>>>(out_proj_w, DD,    14, DD*DD, DD);
    round_w_kernel<<<(DD*DD+255)/256, 256>>>(concat_w,   DD+CC, 15, DD*DD, DD);
    round_w_kernel<<<(DD*H2+255)/256, 256>>>(mix_w2,     H2,    17, DD*H2, H2);
    prep_w1c_kernel<<<(H2*1536+255)/256, 256>>>(mix_w1);

    ln_base_kernel<<<BL, 128>>>(x, film_ln_g, film_ln_b, q_ln_g, q_ln_b);

    // q = xq @ wq^T + bq
    gemm_mma<0,0,false,0><<<dim3(4, 256), 256, GM_SMEM>>>(3, 4, 13, in_proj_b, 10, 0, DD, DD);

    attn_kernel<<<BL, 128>>>();

    // ao = a @ wo^T + bo
    gemm_mma<0,0,false,0><<<dim3(4, 256), 256, GM_SMEM>>>(5, 6, 14, out_proj_b, 12, 0, DD, DD);
    prep_mix_kernel<<<(BL*DD/4+255)/256, 256>>>(x);

    // updc raw = relu(x @ wc^T + ctxadd[b])   (concat-LN folded into final)
    gemm_mma<0,1,true,0><<<dim3(4, 256), 256, GM_SMEM>>>(1, 2, 15, nullptr, 11, 0, DD, DD);

    // mixh = relu([x|ao|x*ao] @ W1c^T + b1), fp16-split output
    gemm_mma<1,0,true,1><<<dim3(8, 256), 256, GM_SMEM>>>(0, 0, 16, mix_b1, 11, 12, H2, 1536);

    // upda = mixh @ w2^T + b2
    gemm_mma<0,0,false,0><<<dim3(4, 256), 256, GM_SMEM>>>(11, 12, 17, mix_b2, 14, 0, DD, H2);

    final_kernel<<<BL, 128>>>(pad_mask, concat_ln_g, concat_ln_b, out_ln_g, out_ln_b, out);

    (void)in_sizes; (void)n_in; (void)out_size;
}

// round 13
// speedup vs baseline: 5.9356x; 1.4745x over previous
#include <cuda_runtime.h>
#include <cuda_bf16.h>
#include <cuda_fp16.h>
#include <math.h>
#include <stdint.h>

#define BB   8
#define LL   4096
#define BL   (BB*LL)
#define DD   512
#define CC   256
#define TT   2
#define HC   512
#define H2   1024
#define LN_EPS 1e-5f

// ---------------- fp32 scratch (ids for gsel; never passed from host) ------
__device__ float g_gb[BB*1024];          // 1
__device__ float g_gate[BB*DD];          // 2
__device__ float g_h[BB*HC];             // 3
__device__ float g_ctxadd[BB*DD];        // 4
__device__ float g_ctxtok[BB*TT*DD];     // 5
__device__ float g_k[BB*TT*DD];          // 6
__device__ float g_v[BB*TT*DD];          // 7
__device__ float g_base[(size_t)BL*DD];  // 8
__device__ float g_q[(size_t)BL*DD];     // 10
__device__ float g_updc[(size_t)BL*DD];  // 11
__device__ float g_ao[(size_t)BL*DD];    // 12
__device__ float g_upda[(size_t)BL*DD];  // 14
__device__ int   g_maskmode;

// ---------------- fp16 scratch (ids for hsel) -------------------------------
__device__ __half h_x  [(size_t)BL*DD];   // 1
__device__ __half h_xq [(size_t)BL*DD];   // 3
__device__ __half h_a  [(size_t)BL*DD];   // 5
__device__ __half h_ao [(size_t)BL*DD];   // 7
__device__ __half h_p  [(size_t)BL*DD];   // 9
__device__ __half h_mh [(size_t)BL*H2];   // 11
__device__ __half h_wq[DD*DD];            // 13
__device__ __half h_wo[DD*DD];            // 14
__device__ __half h_wc[DD*DD];            // 15
__device__ __half h_w1[H2*1536];          // 16
__device__ __half h_w2[DD*H2];            // 17

__device__ __forceinline__ float* gsel(const float* p, int id)
{
    switch (id) {
        case 1: return g_gb;     case 2: return g_gate;   case 3: return g_h;
        case 4: return g_ctxadd; case 5: return g_ctxtok; case 6: return g_k;
        case 7: return g_v;      case 8: return g_base;   case 10: return g_q;
        case 11: return g_updc;  case 12: return g_ao;    case 14: return g_upda;
        default: return const_cast<float*>(p);
    }
}
__device__ __forceinline__ __half* hsel(int id)
{
    switch (id) {
        case 1: return h_x;    case 3: return h_xq;   case 5: return h_a;
        case 7: return h_ao;   case 9: return h_p;    case 11: return h_mh;
        case 13: return h_wq;  case 14: return h_wo;  case 15: return h_wc;
        case 16: return h_w1;  case 17: return h_w2;
        default: return nullptr;
    }
}

__device__ __forceinline__ uint32_t pack2h(__half a, __half b)
{
    return (uint32_t)__half_as_ushort(a) | ((uint32_t)__half_as_ushort(b) << 16);
}
__device__ __forceinline__ uint32_t smem_u32(const void* p)
{
    uint32_t a;
    asm("{ .reg .u64 t; cvta.to.shared.u64 t, %1; cvt.u32.u64 %0, t; }" : "=r"(a) : "l"(p));
    return a;
}

// ---------------- mask dtype detection -------------------------------------
__global__ void detect_mask_kernel(const unsigned char* __restrict__ m)
{
    __shared__ int s_gt1, s_odd;
    if (threadIdx.x == 0) { s_gt1 = 0; s_odd = 0; }
    __syncthreads();
    int lgt1 = 0, lodd = 0;
    for (int i = threadIdx.x; i < BL; i += 256) {
        unsigned char v = m[i];
        if (v > 1) lgt1 = 1;
        if ((i & 3) && v) lodd = 1;
    }
    if (lgt1) atomicOr(&s_gt1, 1);
    if (lodd) atomicOr(&s_odd, 1);
    __syncthreads();
    if (threadIdx.x == 0) g_maskmode = (!s_gt1 && s_odd) ? 1 : 0;
}

// ---------------- context-side small GEMM (warp per output) ----------------
__global__ void small_gemmW(const float* __restrict__ Ap, int Aid, int lda,
                            const float* __restrict__ W, int ldw,
                            const float* __restrict__ bias,
                            int outid, int M, int N, int K, int act)
{
    const float* A = gsel(Ap, Aid);
    float* out = gsel(nullptr, outid);
    int o = blockIdx.x * 8 + (threadIdx.x >> 5);
    if (o >= M * N) return;
    int lane = threadIdx.x & 31;
    int m = o / N, n = o % N;
    const float* a = A + (size_t)m * lda;
    const float* w = W + (size_t)n * ldw;
    float s = 0.f;
    for (int k = lane; k < K; k += 32) s += a[k] * w[k];
    #pragma unroll
    for (int off = 16; off; off >>= 1) s += __shfl_down_sync(0xffffffffu, s, off);
    if (lane == 0) {
        s += bias[n];
        if (act == 1)      s = 0.5f * s * (1.f + erff(s * 0.70710678118654752f));
        else if (act == 2) s = 1.f / (1.f + expf(-s));
        out[o] = s;
    }
}

// ---------------- weight rounding (single fp16) ------------------------------
__global__ void round_w_kernel(const float* __restrict__ src, int ldsrc,
                               int wId, int total, int K)
{
    __half* wh = hsel(wId);
    int i = blockIdx.x * blockDim.x + threadIdx.x;
    if (i >= total) return;
    int n = i / K, k = i % K;
    wh[i] = __float2half_rn(src[(size_t)n * ldsrc + k]);
}

__global__ void prep_w1c_kernel(const float* __restrict__ mw1)
{
    int i = blockIdx.x * blockDim.x + threadIdx.x;
    if (i >= H2 * 1536) return;
    int n = i / 1536, k = i % 1536;
    const float* r = mw1 + (size_t)n * 2048;
    float v;
    if      (k < 512)  v = r[k] + r[k + 1024];
    else if (k < 1024) v = r[k] - r[k + 512];
    else               v = r[k + 512];
    h_w1[i] = __float2half_rn(v);
}

__global__ void prep_mix_kernel(const float* __restrict__ x)
{
    size_t i = (size_t)blockIdx.x * blockDim.x + threadIdx.x;
    if (i >= (size_t)BL * DD / 4) return;
    float4 xv = reinterpret_cast<const float4*>(x)[i];
    float4 av = reinterpret_cast<const float4*>(g_ao)[i];
    reinterpret_cast<uint2*>(h_ao)[i] = make_uint2(
        pack2h(__float2half_rn(av.x), __float2half_rn(av.y)),
        pack2h(__float2half_rn(av.z), __float2half_rn(av.w)));
    reinterpret_cast<uint2*>(h_p)[i] = make_uint2(
        pack2h(__float2half_rn(xv.x*av.x), __float2half_rn(xv.y*av.y)),
        pack2h(__float2half_rn(xv.z*av.z), __float2half_rn(xv.w*av.w)));
}

// ---------------- LN / attention / final -----------------------------------
__device__ __forceinline__ float2 block_reduce2_128(float a, float b)
{
    __shared__ float sa[4], sb[4];
    __syncthreads();
    int lane = threadIdx.x & 31, w = threadIdx.x >> 5;
    #pragma unroll
    for (int o = 16; o; o >>= 1) {
        a += __shfl_down_sync(0xffffffffu, a, o);
        b += __shfl_down_sync(0xffffffffu, b, o);
    }
    if (lane == 0) { sa[w] = a; sb[w] = b; }
    __syncthreads();
    return make_float2(sa[0]+sa[1]+sa[2]+sa[3], sb[0]+sb[1]+sb[2]+sb[3]);
}

__global__ void ln_base_kernel(const float* __restrict__ x,
                               const float* __restrict__ fg, const float* __restrict__ fb,
                               const float* __restrict__ qg, const float* __restrict__ qb)
{
    int row = blockIdx.x;
    int b = row >> 12;
    const float* xr = x + (size_t)row * DD;
    float v[4], s = 0.f, s2 = 0.f;
    #pragma unroll
    for (int i = 0; i < 4; i++) {
        v[i] = xr[threadIdx.x + i * 128];
        s += v[i]; s2 += v[i] * v[i];
    }
    float2 r = block_reduce2_128(s, s2);
    float mean = r.x * (1.f / DD);
    float inv  = rsqrtf(r.y * (1.f / DD) - mean * mean + LN_EPS);
    #pragma unroll
    for (int i = 0; i < 4; i++) {
        int d = threadIdx.x + i * 128;
        size_t idx = (size_t)row * DD + d;
        h_x[idx] = __float2half_rn(v[i]);
        float xh = (v[i] - mean) * inv;
        float lnf = xh * fg[d] + fb[d];
        g_base[idx] = (1.f + g_gb[b*1024 + d]) * lnf + g_gb[b*1024 + 512 + d];
        h_xq[idx] = __float2half_rn(xh * qg[d] + qb[d]);
    }
}

__global__ void attn_kernel()
{
    int row = blockIdx.x;
    int b = row >> 12;
    int tid = threadIdx.x;
    const float* qr = g_q + (size_t)row * DD;
    const float* kb = g_k + b * (TT * DD);
    const float* vb = g_v + b * (TT * DD);
    int d0 = tid, d1 = tid + 128, d2 = tid + 256, d3 = tid + 384;
    float a00, a01, a10, a11;
    {
        float q0 = qr[d0], q1 = qr[d1], q2 = qr[d2], q3 = qr[d3];
        a00 = q0 * kb[d0] + q1 * kb[d1];
        a01 = q0 * kb[512 + d0] + q1 * kb[512 + d1];
        a10 = q2 * kb[d2] + q3 * kb[d3];
        a11 = q2 * kb[512 + d2] + q3 * kb[512 + d3];
    }
    __shared__ float red[4][4];
    int lane = tid & 31, w = tid >> 5;
    #pragma unroll
    for (int o = 16; o; o >>= 1) {
        a00 += __shfl_down_sync(0xffffffffu, a00, o);
        a01 += __shfl_down_sync(0xffffffffu, a01, o);
        a10 += __shfl_down_sync(0xffffffffu, a10, o);
        a11 += __shfl_down_sync(0xffffffffu, a11, o);
    }
    if (lane == 0) { red[w][0]=a00; red[w][1]=a01; red[w][2]=a10; red[w][3]=a11; }
    __syncthreads();
    float s00 = (red[0][0]+red[1][0]+red[2][0]+red[3][0]) * 0.0625f;
    float s01 = (red[0][1]+red[1][1]+red[2][1]+red[3][1]) * 0.0625f;
    float s10 = (red[0][2]+red[1][2]+red[2][2]+red[3][2]) * 0.0625f;
    float s11 = (red[0][3]+red[1][3]+red[2][3]+red[3][3]) * 0.0625f;
    float m0 = fmaxf(s00, s01), m1 = fmaxf(s10, s11);
    float e0a = expf(s00-m0), e0b = expf(s01-m0);
    float e1a = expf(s10-m1), e1b = expf(s11-m1);
    float p00 = e0a/(e0a+e0b), p01 = e0b/(e0a+e0b);
    float p10 = e1a/(e1a+e1b), p11 = e1b/(e1a+e1b);
    size_t rb = (size_t)row * DD;
    h_a[rb+d0] = __float2half_rn(p00*vb[d0] + p01*vb[512+d0]);
    h_a[rb+d1] = __float2half_rn(p00*vb[d1] + p01*vb[512+d1]);
    h_a[rb+d2] = __float2half_rn(p10*vb[d2] + p11*vb[512+d2]);
    h_a[rb+d3] = __float2half_rn(p10*vb[d3] + p11*vb[512+d3]);
}

__global__ void final_kernel(const void* __restrict__ mask,
                             const float* __restrict__ cg, const float* __restrict__ cb,
                             const float* __restrict__ og, const float* __restrict__ ob,
                             float* __restrict__ out)
{
    int row = blockIdx.x;
    int b = row >> 12;
    float mk = (g_maskmode == 1) ? (((const unsigned char*)mask)[row] ? 1.f : 0.f)
                                 : ((((const int*)mask)[row] != 0) ? 1.f : 0.f);
    float u[4], us = 0.f, us2 = 0.f;
    #pragma unroll
    for (int i = 0; i < 4; i++) {
        int d = threadIdx.x + i * 128;
        u[i] = g_updc[(size_t)row * DD + d];
        us += u[i]; us2 += u[i] * u[i];
    }
    float2 ur = block_reduce2_128(us, us2);
    float umean = ur.x * (1.f / DD);
    float uinv  = rsqrtf(ur.y * (1.f / DD) - umean * umean + LN_EPS);
    float v[4], s = 0.f, s2 = 0.f;
    #pragma unroll
    for (int i = 0; i < 4; i++) {
        int d = threadIdx.x + i * 128;
        size_t idx = (size_t)row * DD + d;
        float uln = (u[i] - umean) * uinv * cg[d] + cb[d];
        float val = g_base[idx] + g_gate[b*DD + d] * mk * (uln + g_upda[idx]);
        v[i] = val; s += val; s2 += val * val;
    }
    float2 r = block_reduce2_128(s, s2);
    float mean = r.x * (1.f / DD);
    float inv  = rsqrtf(r.y * (1.f / DD) - mean * mean + LN_EPS);
    #pragma unroll
    for (int i = 0; i < 4; i++) {
        int d = threadIdx.x + i * 128;
        out[(size_t)row * DD + d] = (v[i] - mean) * inv * og[d] + ob[d];
    }
}

// ---------------- mma.sync single-pass fp16 GEMM (ldmatrix fragments) --------
// C[BL, N] = A @ W^T, A and W rounded fp16, fp32 acc.
// 128x128 block tile, 8 warps (2x4), each 64x32, k-chunk 32, cp.async double buf.
#define TSTRIDE 20
#define TILE_U32 (128*TSTRIDE)
#define TILE_B   (TILE_U32*4)
#define GM_SMEM  (4*TILE_B)

__device__ __forceinline__ void cpa16(uint32_t dst, const void* src)
{
    asm volatile("cp.async.cg.shared.global [%0], [%1], 16;" :: "r"(dst), "l"(src) : "memory");
}
__device__ __forceinline__ void load_tile_async(const __half* __restrict__ src, int ld,
                                                int row0, int k0, uint32_t dstb, int tid)
{
    #pragma unroll
    for (int i = 0; i < 2; i++) {
        int idx = i * 256 + tid;
        int rr = idx >> 2;
        int q  = idx & 3;
        cpa16(dstb + rr * (TSTRIDE*4) + q * 16,
              src + (size_t)(row0 + rr) * ld + k0 + q * 8);
    }
}
__device__ __forceinline__ void mma_fp16(float* c, const uint32_t* a, const uint32_t* b)
{
    asm volatile(
        "mma.sync.aligned.m16n8k16.row.col.f32.f16.f16.f32 "
        "{%0,%1,%2,%3}, {%4,%5,%6,%7}, {%8,%9}, {%0,%1,%2,%3};"
        : "+f"(c[0]), "+f"(c[1]), "+f"(c[2]), "+f"(c[3])
        : "r"(a[0]), "r"(a[1]), "r"(a[2]), "r"(a[3]), "r"(b[0]), "r"(b[1]));
}
__device__ __forceinline__ void ldmx4(uint32_t* r, uint32_t addr)
{
    asm volatile("ldmatrix.sync.aligned.m8n8.x4.shared.b16 {%0,%1,%2,%3}, [%4];"
        : "=r"(r[0]), "=r"(r[1]), "=r"(r[2]), "=r"(r[3]) : "r"(addr));
}

template<int AMODE, int EPI, bool RELU, int OMODE>
__global__ void __launch_bounds__(256, 2) gemm_mma(
    int AId, int WId,
    const float* __restrict__ biasPtr,
    int outId, int N, int K)
{
    extern __shared__ uint32_t sm[];
    const int tid  = threadIdx.x;
    const int wid  = tid >> 5;
    const int lane = tid & 31;
    const int wm   = wid >> 2;
    const int wn   = wid & 3;
    const int grp  = lane >> 2;
    const int tig  = lane & 3;
    const int bm   = blockIdx.y * 128;
    const int bn   = blockIdx.x * 128;

    const __half* Wh = hsel(WId);
    const __half* Ah = (AMODE == 0) ? hsel(AId) : nullptr;

    const uint32_t smb = smem_u32(sm);
    const int NCH = K >> 5;

    const int lrow = lane & 7;
    const int lsel = (lane >> 3) & 1;
    const int lhi  = lane >> 4;

    float acc[4][4][4];
    #pragma unroll
    for (int i = 0; i < 4; i++)
        #pragma unroll
        for (int j = 0; j < 4; j++)
            #pragma unroll
            for (int q = 0; q < 4; q++) acc[i][j][q] = 0.f;

    auto issue_chunk = [&](int c) {
        const int buf = c & 1;
        const __half* pA; int ka, lda;
        if (AMODE == 0) { pA = Ah; ka = c * 32; lda = K; }
        else {
            int kg = c * 32, seg = kg >> 9; ka = kg & 511; lda = 512;
            if      (seg == 0) pA = h_x;
            else if (seg == 1) pA = h_ao;
            else               pA = h_p;
        }
        uint32_t base = smb + buf * 2 * TILE_B;
        load_tile_async(pA, lda, bm, ka,   base,          tid);
        load_tile_async(Wh, K,   bn, c*32, base + TILE_B, tid);
        asm volatile("cp.async.commit_group;" ::: "memory");
    };

    issue_chunk(0);
    asm volatile("cp.async.wait_group 0;" ::: "memory");
    __syncthreads();

    for (int c = 0; c < NCH; c++) {
        const int buf = c & 1;
        if (c + 1 < NCH) issue_chunk(c + 1);

        const uint32_t tA = smb + (buf * 2 + 0) * TILE_B;
        const uint32_t tW = smb + (buf * 2 + 1) * TILE_B;

        #pragma unroll
        for (int ks = 0; ks < 2; ks++) {
            const uint32_t aoff = (uint32_t)((lrow + lsel * 8) * (TSTRIDE*4) + ks * 32 + lhi * 16);
            const uint32_t boff = (uint32_t)((lrow + lhi * 8) * (TSTRIDE*4) + ks * 32 + lsel * 16);

            uint32_t ah[4][4], wreg[2][4];
            #pragma unroll
            for (int mi = 0; mi < 4; mi++) {
                uint32_t ro = (uint32_t)((wm * 64 + mi * 16) * (TSTRIDE*4));
                ldmx4(ah[mi], tA + ro + aoff);
            }
            #pragma unroll
            for (int p = 0; p < 2; p++) {
                uint32_t no = (uint32_t)((wn * 32 + p * 16) * (TSTRIDE*4));
                ldmx4(wreg[p], tW + no + boff);
            }
            #pragma unroll
            for (int mi = 0; mi < 4; mi++)
                #pragma unroll
                for (int nj = 0; nj < 4; nj++) {
                    const uint32_t* bh = &wreg[nj >> 1][(nj & 1) * 2];
                    mma_fp16(acc[mi][nj], ah[mi], bh);
                }
        }
        asm volatile("cp.async.wait_group 0;" ::: "memory");
        __syncthreads();
    }

    float* Cf = (OMODE == 0) ? gsel(nullptr, outId) : nullptr;
    __half* Oh = (OMODE == 1) ? hsel(outId) : nullptr;

    #pragma unroll
    for (int mi = 0; mi < 4; mi++) {
        #pragma unroll
        for (int nj = 0; nj < 4; nj++) {
            int n = bn + wn * 32 + nj * 8 + tig * 2;
            #pragma unroll
            for (int half = 0; half < 2; half++) {
                int m = bm + wm * 64 + mi * 16 + grp + half * 8;
                float v0 = acc[mi][nj][half * 2 + 0];
                float v1 = acc[mi][nj][half * 2 + 1];
                float bv0, bv1;
                if (EPI == 0) { bv0 = biasPtr[n]; bv1 = biasPtr[n + 1]; }
                else { bv0 = g_ctxadd[(m >> 12) * DD + n]; bv1 = g_ctxadd[(m >> 12) * DD + n + 1]; }
                v0 += bv0; v1 += bv1;
                if (RELU) { v0 = fmaxf(v0, 0.f); v1 = fmaxf(v1, 0.f); }
                if (OMODE == 0) {
                    *reinterpret_cast<float2*>(&Cf[(size_t)m * N + n]) = make_float2(v0, v1);
                } else {
                    *reinterpret_cast<uint32_t*>(&Oh[(size_t)m * N + n]) =
                        pack2h(__float2half_rn(v0), __float2half_rn(v1));
                }
            }
        }
    }
}

// ---------------- launch ----------------------------------------------------
extern "C" void kernel_launch(void* const* d_in, const int* in_sizes, int n_in,
                              void* d_out, int out_size)
{
    const float* x          = (const float*)d_in[0];
    const float* context    = (const float*)d_in[1];
    const void*  pad_mask   = d_in[2];
    const float* film_ln_g  = (const float*)d_in[3];
    const float* film_ln_b  = (const float*)d_in[4];
    const float* film_w     = (const float*)d_in[5];
    const float* film_b     = (const float*)d_in[6];
    const float* concat_w   = (const float*)d_in[7];
    const float* concat_b   = (const float*)d_in[8];
    const float* concat_ln_g= (const float*)d_in[9];
    const float* concat_ln_b= (const float*)d_in[10];
    const float* ctx_w1     = (const float*)d_in[11];
    const float* ctx_b1     = (const float*)d_in[12];
    const float* ctx_w2     = (const float*)d_in[13];
    const float* ctx_b2     = (const float*)d_in[14];
    const float* q_ln_g     = (const float*)d_in[15];
    const float* q_ln_b     = (const float*)d_in[16];
    const float* in_proj_w  = (const float*)d_in[17];
    const float* in_proj_b  = (const float*)d_in[18];
    const float* out_proj_w = (const float*)d_in[19];
    const float* out_proj_b = (const float*)d_in[20];
    const float* mix_w1     = (const float*)d_in[21];
    const float* mix_b1     = (const float*)d_in[22];
    const float* mix_w2     = (const float*)d_in[23];
    const float* mix_b2     = (const float*)d_in[24];
    const float* out_ln_g   = (const float*)d_in[25];
    const float* out_ln_b   = (const float*)d_in[26];
    const float* gate_w     = (const float*)d_in[27];
    const float* gate_b     = (const float*)d_in[28];
    float* out = (float*)d_out;

    cudaFuncSetAttribute(gemm_mma<0,0,false,0>, cudaFuncAttributeMaxDynamicSharedMemorySize, GM_SMEM);
    cudaFuncSetAttribute(gemm_mma<0,1,true, 0>, cudaFuncAttributeMaxDynamicSharedMemorySize, GM_SMEM);
    cudaFuncSetAttribute(gemm_mma<1,0,true, 1>, cudaFuncAttributeMaxDynamicSharedMemorySize, GM_SMEM);

    detect_mask_kernel<<<1, 256>>>((const unsigned char*)pad_mask);

    small_gemmW<<<(BB*1024+7)/8, 256>>>(context, 0, CC, film_w, CC, film_b, 1, BB, 1024, CC, 0);
    small_gemmW<<<(BB*DD  +7)/8, 256>>>(context, 0, CC, gate_w, CC, gate_b, 2, BB, DD,   CC, 2);
    small_gemmW<<<(BB*HC  +7)/8, 256>>>(context, 0, CC, ctx_w1, CC, ctx_b1, 3, BB, HC,   CC, 1);
    small_gemmW<<<(BB*DD  +7)/8, 256>>>(context, 0, CC, concat_w + DD, DD+CC, concat_b, 4, BB, DD, CC, 0);
    small_gemmW<<<(BB*1024+7)/8, 256>>>(nullptr, 3, HC, ctx_w2, HC, ctx_b2, 5, BB, 1024, HC, 0);
    small_gemmW<<<(BB*TT*DD+7)/8, 256>>>(nullptr, 5, DD, in_proj_w + (size_t)DD*DD,   DD, in_proj_b + DD,   6, BB*TT, DD, DD, 0);
    small_gemmW<<<(BB*TT*DD+7)/8, 256>>>(nullptr, 5, DD, in_proj_w + (size_t)2*DD*DD, DD, in_proj_b + 2*DD, 7, BB*TT, DD, DD, 0);

    round_w_kernel<<<(DD*DD+255)/256, 256>>>(in_proj_w,  DD,    13, DD*DD, DD);
    round_w_kernel<<<(DD*DD+255)/256, 256>>>(out_proj_w, DD,    14, DD*DD, DD);
    round_w_kernel<<<(DD*DD+255)/256, 256>>>(concat_w,   DD+CC, 15, DD*DD, DD);
    round_w_kernel<<<(DD*H2+255)/256, 256>>>(mix_w2,     H2,    17, DD*H2, H2);
    prep_w1c_kernel<<<(H2*1536+255)/256, 256>>>(mix_w1);

    ln_base_kernel<<<BL, 128>>>(x, film_ln_g, film_ln_b, q_ln_g, q_ln_b);

    // q = xq @ wq^T + bq
    gemm_mma<0,0,false,0><<<dim3(4, 256), 256, GM_SMEM>>>(3, 13, in_proj_b, 10, DD, DD);

    attn_kernel<<<BL, 128>>>();

    // ao = a @ wo^T + bo
    gemm_mma<0,0,false,0><<<dim3(4, 256), 256, GM_SMEM>>>(5, 14, out_proj_b, 12, DD, DD);
    prep_mix_kernel<<<(BL*DD/4+255)/256, 256>>>(x);

    // updc raw = relu(x @ wc^T + ctxadd[b])   (concat-LN folded into final)
    gemm_mma<0,1,true,0><<<dim3(4, 256), 256, GM_SMEM>>>(1, 15, nullptr, 11, DD, DD);

    // mixh = relu([x|ao|x*ao] @ W1c^T + b1), fp16 output
    gemm_mma<1,0,true,1><<<dim3(8, 256), 256, GM_SMEM>>>(0, 16, mix_b1, 11, H2, 1536);

    // upda = mixh @ w2^T + b2
    gemm_mma<0,0,false,0><<<dim3(4, 256), 256, GM_SMEM>>>(11, 17, mix_b2, 14, DD, H2);

    final_kernel<<<BL, 128>>>(pad_mask, concat_ln_g, concat_ln_b, out_ln_g, out_ln_b, out);

    (void)in_sizes; (void)n_in; (void)out_size;
}

// round 14
// speedup vs baseline: 6.8499x; 1.1540x over previous
#include <cuda_runtime.h>
#include <cuda_bf16.h>
#include <cuda_fp16.h>
#include <math.h>
#include <stdint.h>

#define BB   8
#define LL   4096
#define BL   (BB*LL)
#define DD   512
#define CC   256
#define TT   2
#define HC   512
#define H2   1024
#define LN_EPS 1e-5f

// ---------------- fp32 scratch (ids for gsel; never passed from host) ------
__device__ float g_gb[BB*1024];          // 1
__device__ float g_gate[BB*DD];          // 2
__device__ float g_h[BB*HC];             // 3
__device__ float g_ctxadd[BB*DD];        // 4
__device__ float g_ctxtok[BB*TT*DD];     // 5
__device__ float g_k[BB*TT*DD];          // 6
__device__ float g_v[BB*TT*DD];          // 7
__device__ float g_base[(size_t)BL*DD];  // 8
__device__ float g_updc[(size_t)BL*DD];  // 11
__device__ float g_upda[(size_t)BL*DD];  // 14
__device__ float g_m[32*DD];             // attention score vectors (b,t,h)
__device__ float g_vo[32*DD];            // out-projected v vectors (b,t,h)
__device__ float g_sb[32];               // per-(b,t,h) score bias
__device__ int   g_maskmode;

// ---------------- fp16 scratch (ids for hsel) -------------------------------
__device__ __half h_x  [(size_t)BL*DD];   // 1
__device__ __half h_ao [(size_t)BL*DD];   // 7
__device__ __half h_p  [(size_t)BL*DD];   // 9
__device__ __half h_mh [(size_t)BL*H2];   // 11
__device__ __half h_wc[DD*DD];            // 15
__device__ __half h_w1[H2*1536];          // 16
__device__ __half h_w2[DD*H2];            // 17

__device__ __forceinline__ float* gsel(const float* p, int id)
{
    switch (id) {
        case 1: return g_gb;     case 2: return g_gate;   case 3: return g_h;
        case 4: return g_ctxadd; case 5: return g_ctxtok; case 6: return g_k;
        case 7: return g_v;      case 8: return g_base;
        case 11: return g_updc;  case 14: return g_upda;
        default: return const_cast<float*>(p);
    }
}
__device__ __forceinline__ __half* hsel(int id)
{
    switch (id) {
        case 1: return h_x;    case 7: return h_ao;   case 9: return h_p;
        case 11: return h_mh;  case 15: return h_wc;  case 16: return h_w1;
        case 17: return h_w2;
        default: return nullptr;
    }
}

__device__ __forceinline__ uint32_t pack2h(__half a, __half b)
{
    return (uint32_t)__half_as_ushort(a) | ((uint32_t)__half_as_ushort(b) << 16);
}
__device__ __forceinline__ uint32_t smem_u32(const void* p)
{
    uint32_t a;
    asm("{ .reg .u64 t; cvta.to.shared.u64 t, %1; cvt.u32.u64 %0, t; }" : "=r"(a) : "l"(p));
    return a;
}

// ---------------- mask dtype detection -------------------------------------
__global__ void detect_mask_kernel(const unsigned char* __restrict__ m)
{
    __shared__ int s_gt1, s_odd;
    if (threadIdx.x == 0) { s_gt1 = 0; s_odd = 0; }
    __syncthreads();
    int lgt1 = 0, lodd = 0;
    for (int i = threadIdx.x; i < BL; i += 256) {
        unsigned char v = m[i];
        if (v > 1) lgt1 = 1;
        if ((i & 3) && v) lodd = 1;
    }
    if (lgt1) atomicOr(&s_gt1, 1);
    if (lodd) atomicOr(&s_odd, 1);
    __syncthreads();
    if (threadIdx.x == 0) g_maskmode = (!s_gt1 && s_odd) ? 1 : 0;
}

// ---------------- context-side small GEMM (warp per output) ----------------
__global__ void small_gemmW(const float* __restrict__ Ap, int Aid, int lda,
                            const float* __restrict__ W, int ldw,
                            const float* __restrict__ bias,
                            int outid, int M, int N, int K, int act)
{
    const float* A = gsel(Ap, Aid);
    float* out = gsel(nullptr, outid);
    int o = blockIdx.x * 8 + (threadIdx.x >> 5);
    if (o >= M * N) return;
    int lane = threadIdx.x & 31;
    int m = o / N, n = o % N;
    const float* a = A + (size_t)m * lda;
    const float* w = W + (size_t)n * ldw;
    float s = 0.f;
    for (int k = lane; k < K; k += 32) s += a[k] * w[k];
    #pragma unroll
    for (int off = 16; off; off >>= 1) s += __shfl_down_sync(0xffffffffu, s, off);
    if (lane == 0) {
        s += bias[n];
        if (act == 1)      s = 0.5f * s * (1.f + erff(s * 0.70710678118654752f));
        else if (act == 2) s = 1.f / (1.f + expf(-s));
        out[o] = s;
    }
}

// ---------------- attention precompute: m vectors + score bias --------------
// idx = b*4 + t*2 + h. m[idx][d] = sum_j wq[h*256+j][d] * k[b,t,h*256+j]
// sb[idx] = sum_j bq[h*256+j] * k[b,t,h*256+j]
__global__ void m_kernel(const float* __restrict__ wq, const float* __restrict__ bq)
{
    int idx = blockIdx.x;
    int h = idx & 1, t = (idx >> 1) & 1, b = idx >> 2;
    __shared__ float sk[256];
    __shared__ float sred[16];
    int tid = threadIdx.x;   // 512
    if (tid < 256) sk[tid] = g_k[(b*2 + t)*512 + h*256 + tid];
    __syncthreads();
    const float* wcol = wq + (size_t)(h*256) * 512 + tid;
    float s = 0.f;
    #pragma unroll 4
    for (int j = 0; j < 256; j++) s += wcol[(size_t)j * 512] * sk[j];
    g_m[idx*512 + tid] = s;
    // score bias reduce
    float pb = (tid < 256) ? bq[h*256 + tid] * sk[tid] : 0.f;
    #pragma unroll
    for (int off = 16; off; off >>= 1) pb += __shfl_down_sync(0xffffffffu, pb, off);
    if ((tid & 31) == 0) sred[tid >> 5] = pb;
    __syncthreads();
    if (tid == 0) {
        float tot = 0.f;
        #pragma unroll
        for (int i = 0; i < 16; i++) tot += sred[i];
        g_sb[idx] = tot;
    }
}

// vo[idx][d] = sum_j wo[d][h*256+j] * v[b,t,h*256+j]   (warp per output)
__global__ void vo_kernel(const float* __restrict__ wo)
{
    int o = blockIdx.x * 8 + (threadIdx.x >> 5);   // 0..16383
    if (o >= 32*512) return;
    int lane = threadIdx.x & 31;
    int d = o & 511, idx = o >> 9;
    int h = idx & 1, t = (idx >> 1) & 1, b = idx >> 2;
    const float* wrow = wo + (size_t)d * 512 + h*256;
    const float* vv = g_v + (b*2 + t)*512 + h*256;
    float s = 0.f;
    #pragma unroll
    for (int j = lane; j < 256; j += 32) s += wrow[j] * vv[j];
    #pragma unroll
    for (int off = 16; off; off >>= 1) s += __shfl_down_sync(0xffffffffu, s, off);
    if (lane == 0) g_vo[o] = s;
}

// ---------------- weight rounding ------------------------------------------
__global__ void round_w_kernel(const float* __restrict__ src, int ldsrc,
                               int wId, int total, int K)
{
    __half* wh = hsel(wId);
    int i = blockIdx.x * blockDim.x + threadIdx.x;
    if (i >= total) return;
    int n = i / K, k = i % K;
    wh[i] = __float2half_rn(src[(size_t)n * ldsrc + k]);
}

__global__ void prep_w1c_kernel(const float* __restrict__ mw1)
{
    int i = blockIdx.x * blockDim.x + threadIdx.x;
    if (i >= H2 * 1536) return;
    int n = i / 1536, k = i % 1536;
    const float* r = mw1 + (size_t)n * 2048;
    float v;
    if      (k < 512)  v = r[k] + r[k + 1024];
    else if (k < 1024) v = r[k] - r[k + 512];
    else               v = r[k + 512];
    h_w1[i] = __float2half_rn(v);
}

// ---------------- fused LN + film base + attention + mix prep ---------------
__device__ __forceinline__ float2 block_reduce2_128(float a, float b)
{
    __shared__ float sa[4], sb[4];
    __syncthreads();
    int lane = threadIdx.x & 31, w = threadIdx.x >> 5;
    #pragma unroll
    for (int o = 16; o; o >>= 1) {
        a += __shfl_down_sync(0xffffffffu, a, o);
        b += __shfl_down_sync(0xffffffffu, b, o);
    }
    if (lane == 0) { sa[w] = a; sb[w] = b; }
    __syncthreads();
    return make_float2(sa[0]+sa[1]+sa[2]+sa[3], sb[0]+sb[1]+sb[2]+sb[3]);
}

__global__ void ln_base_attn_kernel(const float* __restrict__ x,
                                    const float* __restrict__ fg, const float* __restrict__ fb,
                                    const float* __restrict__ qg, const float* __restrict__ qb,
                                    const float* __restrict__ bo)
{
    int row = blockIdx.x;
    int b = row >> 12;
    int tid = threadIdx.x;
    const float* xr = x + (size_t)row * DD;
    float v[4], s = 0.f, s2 = 0.f;
    #pragma unroll
    for (int i = 0; i < 4; i++) {
        v[i] = xr[tid + i * 128];
        s += v[i]; s2 += v[i] * v[i];
    }
    float2 r = block_reduce2_128(s, s2);
    float mean = r.x * (1.f / DD);
    float inv  = rsqrtf(r.y * (1.f / DD) - mean * mean + LN_EPS);

    float xq[4];
    #pragma unroll
    for (int i = 0; i < 4; i++) {
        int d = tid + i * 128;
        size_t idx = (size_t)row * DD + d;
        h_x[idx] = __float2half_rn(v[i]);
        float xh = (v[i] - mean) * inv;
        float lnf = xh * fg[d] + fb[d];
        g_base[idx] = (1.f + g_gb[b*1024 + d]) * lnf + g_gb[b*1024 + 512 + d];
        xq[i] = xh * qg[d] + qb[d];
    }

    // 4 score dot-products: idx offset = b*4 + t*2 + h
    float sc0 = 0.f, sc1 = 0.f, sc2 = 0.f, sc3 = 0.f;
    #pragma unroll
    for (int i = 0; i < 4; i++) {
        int d = tid + i * 128;
        float xqv = xq[i];
        sc0 += xqv * g_m[(b*4 + 0)*512 + d];
        sc1 += xqv * g_m[(b*4 + 1)*512 + d];
        sc2 += xqv * g_m[(b*4 + 2)*512 + d];
        sc3 += xqv * g_m[(b*4 + 3)*512 + d];
    }
    __shared__ float red[4][4];
    int lane = tid & 31, w = tid >> 5;
    #pragma unroll
    for (int o = 16; o; o >>= 1) {
        sc0 += __shfl_down_sync(0xffffffffu, sc0, o);
        sc1 += __shfl_down_sync(0xffffffffu, sc1, o);
        sc2 += __shfl_down_sync(0xffffffffu, sc2, o);
        sc3 += __shfl_down_sync(0xffffffffu, sc3, o);
    }
    __syncthreads();
    if (lane == 0) { red[w][0]=sc0; red[w][1]=sc1; red[w][2]=sc2; red[w][3]=sc3; }
    __syncthreads();
    // scores: (dot + sb) / 16
    float s00 = (red[0][0]+red[1][0]+red[2][0]+red[3][0] + g_sb[b*4+0]) * 0.0625f; // t0 h0
    float s01 = (red[0][1]+red[1][1]+red[2][1]+red[3][1] + g_sb[b*4+1]) * 0.0625f; // t0 h1
    float s10 = (red[0][2]+red[1][2]+red[2][2]+red[3][2] + g_sb[b*4+2]) * 0.0625f; // t1 h0
    float s11 = (red[0][3]+red[1][3]+red[2][3]+red[3][3] + g_sb[b*4+3]) * 0.0625f; // t1 h1

    // softmax over t per head
    float m0 = fmaxf(s00, s10), m1 = fmaxf(s01, s11);
    float e00 = expf(s00 - m0), e10 = expf(s10 - m0);
    float e01 = expf(s01 - m1), e11 = expf(s11 - m1);
    float p00 = e00/(e00+e10), p01 = e10/(e00+e10);  // head0: weight of t0, t1
    float p10 = e01/(e01+e11), p11 = e11/(e01+e11);  // head1: weight of t0, t1

    #pragma unroll
    for (int i = 0; i < 4; i++) {
        int d = tid + i * 128;
        size_t idx = (size_t)row * DD + d;
        float ao = p00 * g_vo[(b*4 + 0)*512 + d]   // t0 h0
                 + p10 * g_vo[(b*4 + 1)*512 + d]   // t0 h1
                 + p01 * g_vo[(b*4 + 2)*512 + d]   // t1 h0
                 + p11 * g_vo[(b*4 + 3)*512 + d]   // t1 h1
                 + bo[d];
        h_ao[idx] = __float2half_rn(ao);
        h_p [idx] = __float2half_rn(v[i] * ao);
    }
}

// ---------------- final ------------------------------------------------------
__global__ void final_kernel(const void* __restrict__ mask,
                             const float* __restrict__ cg, const float* __restrict__ cb,
                             const float* __restrict__ og, const float* __restrict__ ob,
                             float* __restrict__ out)
{
    int row = blockIdx.x;
    int b = row >> 12;
    float mk = (g_maskmode == 1) ? (((const unsigned char*)mask)[row] ? 1.f : 0.f)
                                 : ((((const int*)mask)[row] != 0) ? 1.f : 0.f);
    float u[4], us = 0.f, us2 = 0.f;
    #pragma unroll
    for (int i = 0; i < 4; i++) {
        int d = threadIdx.x + i * 128;
        u[i] = g_updc[(size_t)row * DD + d];
        us += u[i]; us2 += u[i] * u[i];
    }
    float2 ur = block_reduce2_128(us, us2);
    float umean = ur.x * (1.f / DD);
    float uinv  = rsqrtf(ur.y * (1.f / DD) - umean * umean + LN_EPS);
    float v[4], s = 0.f, s2 = 0.f;
    #pragma unroll
    for (int i = 0; i < 4; i++) {
        int d = threadIdx.x + i * 128;
        size_t idx = (size_t)row * DD + d;
        float uln = (u[i] - umean) * uinv * cg[d] + cb[d];
        float val = g_base[idx] + g_gate[b*DD + d] * mk * (uln + g_upda[idx]);
        v[i] = val; s += val; s2 += val * val;
    }
    float2 r = block_reduce2_128(s, s2);
    float mean = r.x * (1.f / DD);
    float inv  = rsqrtf(r.y * (1.f / DD) - mean * mean + LN_EPS);
    #pragma unroll
    for (int i = 0; i < 4; i++) {
        int d = threadIdx.x + i * 128;
        out[(size_t)row * DD + d] = (v[i] - mean) * inv * og[d] + ob[d];
    }
}

// ---------------- mma.sync single-pass fp16 GEMM (ldmatrix fragments) --------
#define TSTRIDE 20
#define TILE_U32 (128*TSTRIDE)
#define TILE_B   (TILE_U32*4)
#define GM_SMEM  (4*TILE_B)

__device__ __forceinline__ void cpa16(uint32_t dst, const void* src)
{
    asm volatile("cp.async.cg.shared.global [%0], [%1], 16;" :: "r"(dst), "l"(src) : "memory");
}
__device__ __forceinline__ void load_tile_async(const __half* __restrict__ src, int ld,
                                                int row0, int k0, uint32_t dstb, int tid)
{
    #pragma unroll
    for (int i = 0; i < 2; i++) {
        int idx = i * 256 + tid;
        int rr = idx >> 2;
        int q  = idx & 3;
        cpa16(dstb + rr * (TSTRIDE*4) + q * 16,
              src + (size_t)(row0 + rr) * ld + k0 + q * 8);
    }
}
__device__ __forceinline__ void mma_fp16(float* c, const uint32_t* a, const uint32_t* b)
{
    asm volatile(
        "mma.sync.aligned.m16n8k16.row.col.f32.f16.f16.f32 "
        "{%0,%1,%2,%3}, {%4,%5,%6,%7}, {%8,%9}, {%0,%1,%2,%3};"
        : "+f"(c[0]), "+f"(c[1]), "+f"(c[2]), "+f"(c[3])
        : "r"(a[0]), "r"(a[1]), "r"(a[2]), "r"(a[3]), "r"(b[0]), "r"(b[1]));
}
__device__ __forceinline__ void ldmx4(uint32_t* r, uint32_t addr)
{
    asm volatile("ldmatrix.sync.aligned.m8n8.x4.shared.b16 {%0,%1,%2,%3}, [%4];"
        : "=r"(r[0]), "=r"(r[1]), "=r"(r[2]), "=r"(r[3]) : "r"(addr));
}

template<int AMODE, int EPI, bool RELU, int OMODE>
__global__ void __launch_bounds__(256, 2) gemm_mma(
    int AId, int WId,
    const float* __restrict__ biasPtr,
    int outId, int N, int K)
{
    extern __shared__ uint32_t sm[];
    const int tid  = threadIdx.x;
    const int wid  = tid >> 5;
    const int lane = tid & 31;
    const int wm   = wid >> 2;
    const int wn   = wid & 3;
    const int grp  = lane >> 2;
    const int tig  = lane & 3;
    const int bm   = blockIdx.y * 128;
    const int bn   = blockIdx.x * 128;

    const __half* Wh = hsel(WId);
    const __half* Ah = (AMODE == 0) ? hsel(AId) : nullptr;

    const uint32_t smb = smem_u32(sm);
    const int NCH = K >> 5;

    const int lrow = lane & 7;
    const int lsel = (lane >> 3) & 1;
    const int lhi  = lane >> 4;

    float acc[4][4][4];
    #pragma unroll
    for (int i = 0; i < 4; i++)
        #pragma unroll
        for (int j = 0; j < 4; j++)
            #pragma unroll
            for (int q = 0; q < 4; q++) acc[i][j][q] = 0.f;

    auto issue_chunk = [&](int c) {
        const int buf = c & 1;
        const __half* pA; int ka, lda;
        if (AMODE == 0) { pA = Ah; ka = c * 32; lda = K; }
        else {
            int kg = c * 32, seg = kg >> 9; ka = kg & 511; lda = 512;
            if      (seg == 0) pA = h_x;
            else if (seg == 1) pA = h_ao;
            else               pA = h_p;
        }
        uint32_t base = smb + buf * 2 * TILE_B;
        load_tile_async(pA, lda, bm, ka,   base,          tid);
        load_tile_async(Wh, K,   bn, c*32, base + TILE_B, tid);
        asm volatile("cp.async.commit_group;" ::: "memory");
    };

    issue_chunk(0);
    asm volatile("cp.async.wait_group 0;" ::: "memory");
    __syncthreads();

    for (int c = 0; c < NCH; c++) {
        const int buf = c & 1;
        if (c + 1 < NCH) issue_chunk(c + 1);

        const uint32_t tA = smb + (buf * 2 + 0) * TILE_B;
        const uint32_t tW = smb + (buf * 2 + 1) * TILE_B;

        #pragma unroll
        for (int ks = 0; ks < 2; ks++) {
            const uint32_t aoff = (uint32_t)((lrow + lsel * 8) * (TSTRIDE*4) + ks * 32 + lhi * 16);
            const uint32_t boff = (uint32_t)((lrow + lhi * 8) * (TSTRIDE*4) + ks * 32 + lsel * 16);

            uint32_t ah[4][4], wreg[2][4];
            #pragma unroll
            for (int mi = 0; mi < 4; mi++) {
                uint32_t ro = (uint32_t)((wm * 64 + mi * 16) * (TSTRIDE*4));
                ldmx4(ah[mi], tA + ro + aoff);
            }
            #pragma unroll
            for (int p = 0; p < 2; p++) {
                uint32_t no = (uint32_t)((wn * 32 + p * 16) * (TSTRIDE*4));
                ldmx4(wreg[p], tW + no + boff);
            }
            #pragma unroll
            for (int mi = 0; mi < 4; mi++)
                #pragma unroll
                for (int nj = 0; nj < 4; nj++) {
                    const uint32_t* bh = &wreg[nj >> 1][(nj & 1) * 2];
                    mma_fp16(acc[mi][nj], ah[mi], bh);
                }
        }
        asm volatile("cp.async.wait_group 0;" ::: "memory");
        __syncthreads();
    }

    float* Cf = (OMODE == 0) ? gsel(nullptr, outId) : nullptr;
    __half* Oh = (OMODE == 1) ? hsel(outId) : nullptr;

    #pragma unroll
    for (int mi = 0; mi < 4; mi++) {
        #pragma unroll
        for (int nj = 0; nj < 4; nj++) {
            int n = bn + wn * 32 + nj * 8 + tig * 2;
            #pragma unroll
            for (int half = 0; half < 2; half++) {
                int m = bm + wm * 64 + mi * 16 + grp + half * 8;
                float v0 = acc[mi][nj][half * 2 + 0];
                float v1 = acc[mi][nj][half * 2 + 1];
                float bv0, bv1;
                if (EPI == 0) { bv0 = biasPtr[n]; bv1 = biasPtr[n + 1]; }
                else { bv0 = g_ctxadd[(m >> 12) * DD + n]; bv1 = g_ctxadd[(m >> 12) * DD + n + 1]; }
                v0 += bv0; v1 += bv1;
                if (RELU) { v0 = fmaxf(v0, 0.f); v1 = fmaxf(v1, 0.f); }
                if (OMODE == 0) {
                    *reinterpret_cast<float2*>(&Cf[(size_t)m * N + n]) = make_float2(v0, v1);
                } else {
                    *reinterpret_cast<uint32_t*>(&Oh[(size_t)m * N + n]) =
                        pack2h(__float2half_rn(v0), __float2half_rn(v1));
                }
            }
        }
    }
}

// ---------------- launch ----------------------------------------------------
extern "C" void kernel_launch(void* const* d_in, const int* in_sizes, int n_in,
                              void* d_out, int out_size)
{
    const float* x          = (const float*)d_in[0];
    const float* context    = (const float*)d_in[1];
    const void*  pad_mask   = d_in[2];
    const float* film_ln_g  = (const float*)d_in[3];
    const float* film_ln_b  = (const float*)d_in[4];
    const float* film_w     = (const float*)d_in[5];
    const float* film_b     = (const float*)d_in[6];
    const float* concat_w   = (const float*)d_in[7];
    const float* concat_b   = (const float*)d_in[8];
    const float* concat_ln_g= (const float*)d_in[9];
    const float* concat_ln_b= (const float*)d_in[10];
    const float* ctx_w1     = (const float*)d_in[11];
    const float* ctx_b1     = (const float*)d_in[12];
    const float* ctx_w2     = (const float*)d_in[13];
    const float* ctx_b2     = (const float*)d_in[14];
    const float* q_ln_g     = (const float*)d_in[15];
    const float* q_ln_b     = (const float*)d_in[16];
    const float* in_proj_w  = (const float*)d_in[17];
    const float* in_proj_b  = (const float*)d_in[18];
    const float* out_proj_w = (const float*)d_in[19];
    const float* out_proj_b = (const float*)d_in[20];
    const float* mix_w1     = (const float*)d_in[21];
    const float* mix_b1     = (const float*)d_in[22];
    const float* mix_w2     = (const float*)d_in[23];
    const float* mix_b2     = (const float*)d_in[24];
    const float* out_ln_g   = (const float*)d_in[25];
    const float* out_ln_b   = (const float*)d_in[26];
    const float* gate_w     = (const float*)d_in[27];
    const float* gate_b     = (const float*)d_in[28];
    float* out = (float*)d_out;

    cudaFuncSetAttribute(gemm_mma<0,0,false,0>, cudaFuncAttributeMaxDynamicSharedMemorySize, GM_SMEM);
    cudaFuncSetAttribute(gemm_mma<0,1,true, 0>, cudaFuncAttributeMaxDynamicSharedMemorySize, GM_SMEM);
    cudaFuncSetAttribute(gemm_mma<1,0,true, 1>, cudaFuncAttributeMaxDynamicSharedMemorySize, GM_SMEM);

    detect_mask_kernel<<<1, 256>>>((const unsigned char*)pad_mask);

    // context-side small GEMMs
    small_gemmW<<<(BB*1024+7)/8, 256>>>(context, 0, CC, film_w, CC, film_b, 1, BB, 1024, CC, 0);
    small_gemmW<<<(BB*DD  +7)/8, 256>>>(context, 0, CC, gate_w, CC, gate_b, 2, BB, DD,   CC, 2);
    small_gemmW<<<(BB*HC  +7)/8, 256>>>(context, 0, CC, ctx_w1, CC, ctx_b1, 3, BB, HC,   CC, 1);
    small_gemmW<<<(BB*DD  +7)/8, 256>>>(context, 0, CC, concat_w + DD, DD+CC, concat_b, 4, BB, DD, CC, 0);
    small_gemmW<<<(BB*1024+7)/8, 256>>>(nullptr, 3, HC, ctx_w2, HC, ctx_b2, 5, BB, 1024, HC, 0);
    small_gemmW<<<(BB*TT*DD+7)/8, 256>>>(nullptr, 5, DD, in_proj_w + (size_t)DD*DD,   DD, in_proj_b + DD,   6, BB*TT, DD, DD, 0);
    small_gemmW<<<(BB*TT*DD+7)/8, 256>>>(nullptr, 5, DD, in_proj_w + (size_t)2*DD*DD, DD, in_proj_b + 2*DD, 7, BB*TT, DD, DD, 0);

    // attention precompute (needs g_k, g_v)
    m_kernel<<<32, 512>>>(in_proj_w, in_proj_b);
    vo_kernel<<<(32*512+7)/8, 256>>>(out_proj_w);

    // weight rounding
    round_w_kernel<<<(DD*DD+255)/256, 256>>>(concat_w, DD+CC, 15, DD*DD, DD);
    round_w_kernel<<<(DD*H2+255)/256, 256>>>(mix_w2,   H2,    17, DD*H2, H2);
    prep_w1c_kernel<<<(H2*1536+255)/256, 256>>>(mix_w1);

    // fused LN + film base + attention + mix prep
    ln_base_attn_kernel<<<BL, 128>>>(x, film_ln_g, film_ln_b, q_ln_g, q_ln_b, out_proj_b);

    // updc raw = relu(x @ wc^T + ctxadd[b])   (concat-LN folded into final)
    gemm_mma<0,1,true,0><<<dim3(4, 256), 256, GM_SMEM>>>(1, 15, nullptr, 11, DD, DD);

    // mixh = relu([x|ao|x*ao] @ W1c^T + b1), fp16 output
    gemm_mma<1,0,true,1><<<dim3(8, 256), 256, GM_SMEM>>>(0, 16, mix_b1, 11, H2, 1536);

    // upda = mixh @ w2^T + b2
    gemm_mma<0,0,false,0><<<dim3(4, 256), 256, GM_SMEM>>>(11, 17, mix_b2, 14, DD, H2);

    final_kernel<<<BL, 128>>>(pad_mask, concat_ln_g, concat_ln_b, out_ln_g, out_ln_b, out);

    (void)in_sizes; (void)n_in; (void)out_size;
}